// round 14
// baseline (speedup 1.0000x reference)
#include <cuda_runtime.h>
#include <cuda_fp16.h>
#include <mma.h>
#include <cstdint>
#include <math.h>

using namespace nvcuda;

#define B_    32
#define V_    32000
#define EMB_  512
#define H_    1024
#define T_    100
#define KG    2048
#define GROWS 4096
#define KSPL  8
#define GRB   64
#define LRB   64
#define NBLK  (V_ / LRB)     // 500
#define KC    64
#define STG   3
#define NPB   16
#define VCH   (V_ / NPB)
#define DELTA 0.05f

#define ALD   72             // padded row stride in halves (tile + smem)
#define BLD   40             // B smem row stride (halves)
#define TILEH (GRB * ALD)    // 4608 halves per tile
#define TILEB (TILEH * 2)    // 9216 bytes per tile

#define SM_B2   81920        // byte offset of A-tile region in dyn smem
#define SM_MBAR 109568
#define SMEMSZ  109600

// ---------------- static device state ----------------
__device__ __align__(128) half  g_wchi2[64 * 32 * TILEH];          // 18.9 MB blob
__device__ __align__(128) half  g_wclo2[64 * 32 * TILEH];          // 18.9 MB blob
__device__ __align__(128) half  g_wo2[(size_t)NBLK * 16 * TILEH];  // 73.7 MB blob
__device__ __align__(128) half  g_x_hi[KG * B_];
__device__ __align__(128) half  g_x_lo[KG * B_];
__device__ __align__(128) float g_part[(size_t)KSPL * GROWS * B_]; // 4 MB
__device__ __align__(128) float g_logits[B_ * V_];
__device__ __align__(128) float g_c[H_ * B_];
__device__ __align__(128) float g_hf[B_ * H_];
__device__ int    g_s[B_];
__device__ float2 g_cM[B_ * NBLK];
__device__ float4 g_cT[B_ * NBLK];

// ---------------- async-copy / mbarrier helpers ----------------
__device__ __forceinline__ void cp16(void* sdst, const void* gsrc) {
  uint32_t d = (uint32_t)__cvta_generic_to_shared(sdst);
  asm volatile("cp.async.cg.shared.global [%0], [%1], 16;\n" :: "r"(d), "l"(gsrc));
}
#define CP_COMMIT() asm volatile("cp.async.commit_group;\n" ::: "memory")
#define CP_WAIT(n)  asm volatile("cp.async.wait_group %0;\n" :: "n"(n) : "memory")

#define MBAR_INIT(addr, cnt) \
  asm volatile("mbarrier.init.shared.b64 [%0], %1;" :: "r"(addr), "r"(cnt) : "memory")
#define MBAR_EXPECT(addr, bytes) \
  asm volatile("mbarrier.arrive.expect_tx.shared.b64 _, [%0], %1;" :: "r"(addr), "r"(bytes) : "memory")

__device__ __forceinline__ void mbar_wait(uint32_t mbar, uint32_t parity) {
  asm volatile(
      "{\n\t.reg .pred P;\n"
      "W%=:\n\tmbarrier.try_wait.parity.shared::cta.b64 P, [%0], %1;\n"
      "\t@!P bra W%=;\n}"
      :: "r"(mbar), "r"(parity) : "memory");
}
__device__ __forceinline__ void bulkcp(uint32_t sdst, const void* gsrc,
                                       uint32_t bytes, uint32_t mbar) {
  asm volatile(
      "cp.async.bulk.shared::cta.global.mbarrier::complete_tx::bytes [%0], [%1], %2, [%3];"
      :: "r"(sdst), "l"(gsrc), "r"(bytes), "r"(mbar) : "memory");
}

// ---------------- threefry / misc ----------------
__host__ __device__ inline void tf2x32(uint32_t k0, uint32_t k1, uint32_t x0, uint32_t x1,
                                       uint32_t &o0, uint32_t &o1) {
  uint32_t ks2 = k0 ^ k1 ^ 0x1BD11BDAu;
  x0 += k0; x1 += k1;
#define TF_R(r) do { x0 += x1; x1 = (x1 << (r)) | (x1 >> (32 - (r))); x1 ^= x0; } while (0)
  TF_R(13); TF_R(15); TF_R(26); TF_R(6);
  x0 += k1;  x1 += ks2 + 1u;
  TF_R(17); TF_R(29); TF_R(16); TF_R(24);
  x0 += ks2; x1 += k0 + 2u;
  TF_R(13); TF_R(15); TF_R(26); TF_R(6);
  x0 += k0;  x1 += k1 + 3u;
  TF_R(17); TF_R(29); TF_R(16); TF_R(24);
  x0 += k1;  x1 += ks2 + 4u;
  TF_R(13); TF_R(15); TF_R(26); TF_R(6);
  x0 += ks2; x1 += k0 + 5u;
#undef TF_R
  o0 = x0; o1 = x1;
}

__device__ __forceinline__ float gumbel_of(uint32_t k0, uint32_t k1, uint32_t i) {
  uint32_t a, b;
  tf2x32(k0, k1, 0u, i, a, b);
  uint32_t bits = a ^ b;
  float u = __uint_as_float((bits >> 9) | 0x3f800000u) - 1.0f;
  const float tiny = 1.17549435e-38f;
  float val = fmaxf(tiny, u * (1.0f - tiny) + tiny);
  return -logf(-logf(val));
}

__device__ __forceinline__ float sigm(float x) { return 1.0f / (1.0f + expf(-x)); }

__device__ __forceinline__ void merge2(float &v1, int &i1, float &v2, int &i2,
                                       float b1, int j1, float b2, int j2) {
  float n1, n2; int m1, m2;
  bool bf = (b1 > v1) || (b1 == v1 && j1 < i1);
  if (bf) { n1 = b1; m1 = j1; bool tk = (v1 > b2) || (v1 == b2 && i1 < j2);
            n2 = tk ? v1 : b2; m2 = tk ? i1 : j2; }
  else    { n1 = v1; m1 = i1; bool tk = (b1 > v2) || (b1 == v2 && j1 < i2);
            n2 = tk ? b1 : v2; m2 = tk ? j1 : i2; }
  v1 = n1; i1 = m1; v2 = n2; i2 = m2;
}

// ---------------- conversion into contiguous tiles ----------------
// gates blob: tile = grp*32 + ck  (grp: 64 rows; ck: k-chunk of 64 in [0,2048))
// within tile: r*ALD + k (k<64 data, 64..71 zero pad)
__global__ void k_conv_comb(const float* __restrict__ w_ih, const float* __restrict__ w_hh) {
  size_t total = (size_t)64 * 32 * (TILEH / 2);
  for (size_t p = blockIdx.x * blockDim.x + threadIdx.x; p < total;
       p += (size_t)gridDim.x * blockDim.x) {
    size_t tile = p / (TILEH / 2);
    int q = (int)(p % (TILEH / 2));
    int r = q / (ALD / 2), kp = (q % (ALD / 2)) * 2;
    int grp = (int)(tile >> 5), ck = (int)(tile & 31);
    half2 hi = __halves2half2(__float2half(0.f), __float2half(0.f));
    half2 lo = hi;
    if (kp < KC) {
      int col = ck * KC + kp;
      int sr = grp * GRB + r;
      float v0, v1;
      if (col < 1024) { v0 = __ldcs(w_ih + (size_t)sr * 1024 + col);
                        v1 = __ldcs(w_ih + (size_t)sr * 1024 + col + 1); }
      else            { v0 = __ldcs(w_hh + (size_t)sr * 1024 + col - 1024);
                        v1 = __ldcs(w_hh + (size_t)sr * 1024 + col - 1023); }
      half h0 = __float2half(v0), h1 = __float2half(v1);
      hi = __halves2half2(h0, h1);
      lo = __halves2half2(__float2half(v0 - __half2float(h0)),
                          __float2half(v1 - __half2float(h1)));
    }
    size_t off = tile * TILEH + (size_t)r * ALD + kp;
    *(half2*)&g_wchi2[off] = hi;
    *(half2*)&g_wclo2[off] = lo;
  }
}
// logits blob: tile = blk*16 + c (blk: 64 rows of V; c: k-chunk of 64 in [0,1024))
__global__ void k_conv_wout(const float* __restrict__ w) {
  size_t total = (size_t)NBLK * 16 * (TILEH / 2);
  for (size_t p = blockIdx.x * blockDim.x + threadIdx.x; p < total;
       p += (size_t)gridDim.x * blockDim.x) {
    size_t tile = p / (TILEH / 2);
    int q = (int)(p % (TILEH / 2));
    int r = q / (ALD / 2), kp = (q % (ALD / 2)) * 2;
    int blk = (int)(tile >> 4), c = (int)(tile & 15);
    half2 h = __halves2half2(__float2half(0.f), __float2half(0.f));
    if (kp < KC) {
      const float* src = w + (size_t)(blk * LRB + r) * H_ + c * KC + kp;
      h = __halves2half2(__float2half(__ldcs(src)), __float2half(__ldcs(src + 1)));
    }
    *(half2*)&g_wo2[tile * TILEH + (size_t)r * ALD + kp] = h;
  }
}
__global__ void k_init(const float* __restrict__ z, const int* __restrict__ sid,
                       const float* __restrict__ emb) {
  int idx = blockIdx.x * blockDim.x + threadIdx.x;
  if (idx < H_ * B_) {
    g_c[idx] = 0.0f;
    g_x_hi[H_ * B_ + idx] = __float2half(0.0f);
    g_x_lo[H_ * B_ + idx] = __float2half(0.0f);
    int b = idx & 31, hid = idx >> 5;
    g_hf[b * H_ + hid] = 0.0f;
  }
  if (idx < EMB_ * B_) {
    int b = idx & 31, k = idx >> 5;
    float v = z[b * EMB_ + k];
    half hi = __float2half(v);
    g_x_hi[(EMB_ + k) * B_ + b] = hi;
    g_x_lo[(EMB_ + k) * B_ + b] = __float2half(v - __half2float(hi));
    int tok = sid ? sid[0] : 0;
    float e = emb[tok * EMB_ + k];
    half ehi = __float2half(e);
    g_x_hi[k * B_ + b] = ehi;
    g_x_lo[k * B_ + b] = __float2half(e - __half2float(ehi));
  }
  if (idx < B_) g_s[idx] = sid ? sid[0] : 0;
}

// ---- gates GEMM (bulk-copy A pipeline).  grid (64, 8), block 128 ------------
// slices 0..3: Whi (k=(ks&3)*512) vs xhi AND xlo;  4..7: Wlo vs xhi.
__global__ void k_gates(int t) {
  extern __shared__ char smc[];
  half* Bh = (half*)smc;                       // 512*BLD
  half* Bl = (half*)(smc + 40960);             // 512*BLD
  half* As = (half*)(smc + SM_B2);             // STG tiles
  uint32_t smA   = (uint32_t)__cvta_generic_to_shared(As);
  uint32_t mbar0 = (uint32_t)__cvta_generic_to_shared(smc + SM_MBAR);
  int grp = blockIdx.x;
  if (t & 1) grp = 63 - grp;
  const int row0 = grp * GRB;
  const int ks = blockIdx.y;
  const int tid = threadIdx.x, w = tid >> 5;
  const bool hiPhase = ks < 4;
  const half* blob = hiPhase ? g_wchi2 : g_wclo2;
  const int kk0 = (ks & 3) * 512;
  const int tbase = grp * 32 + (ks & 3) * 8;
  const int NCHK = 512 / KC;                   // 8

  if (tid == 0)
    for (int s = 0; s < STG; s++) MBAR_INIT(mbar0 + 8 * s, 1);
  __syncthreads();

  // B slice preload (once)
  for (int i = tid; i < 512 * 4; i += 128) {
    int r = i >> 2, cc = i & 3;
    cp16(Bh + r * BLD + cc * 8, g_x_hi + (kk0 + r) * B_ + cc * 8);
  }
  if (hiPhase)
    for (int i = tid; i < 512 * 4; i += 128) {
      int r = i >> 2, cc = i & 3;
      cp16(Bl + r * BLD + cc * 8, g_x_lo + (kk0 + r) * B_ + cc * 8);
    }
  CP_COMMIT();

  if (tid == 0)
    for (int c = 0; c < STG; c++) {
      MBAR_EXPECT(mbar0 + 8 * c, TILEB);
      bulkcp(smA + c * TILEB, blob + (size_t)(tbase + c) * TILEH, TILEB, mbar0 + 8 * c);
    }
  CP_WAIT(0);
  __syncthreads();

  wmma::fragment<wmma::accumulator, 16, 16, 16, float> fc0, fc1;
  wmma::fill_fragment(fc0, 0.0f); wmma::fill_fragment(fc1, 0.0f);

  for (int c = 0; c < NCHK; c++) {
    int s = c % STG;
    mbar_wait(mbar0 + 8 * s, (c / STG) & 1);
    half* as = As + s * TILEH;
    wmma::fragment<wmma::matrix_a, 16, 16, 16, half, wmma::row_major> fa;
    wmma::fragment<wmma::matrix_b, 16, 16, 16, half, wmma::row_major> fb0, fb1;
#pragma unroll
    for (int k4 = 0; k4 < KC / 16; k4++) {
      int brow = c * KC + k4 * 16;
      wmma::load_matrix_sync(fa, as + (w * 16) * ALD + k4 * 16, ALD);
      wmma::load_matrix_sync(fb0, Bh + brow * BLD + 0, BLD);
      wmma::load_matrix_sync(fb1, Bh + brow * BLD + 16, BLD);
      wmma::mma_sync(fc0, fa, fb0, fc0);
      wmma::mma_sync(fc1, fa, fb1, fc1);
      if (hiPhase) {
        wmma::load_matrix_sync(fb0, Bl + brow * BLD + 0, BLD);
        wmma::load_matrix_sync(fb1, Bl + brow * BLD + 16, BLD);
        wmma::mma_sync(fc0, fa, fb0, fc0);
        wmma::mma_sync(fc1, fa, fb1, fc1);
      }
    }
    __syncthreads();
    if (c + STG < NCHK && tid == 0) {
      MBAR_EXPECT(mbar0 + 8 * s, TILEB);
      bulkcp(smA + s * TILEB, blob + (size_t)(tbase + c + STG) * TILEH, TILEB, mbar0 + 8 * s);
    }
  }
  float* dst = g_part + ((size_t)ks * GROWS + row0 + w * 16) * B_;
  wmma::store_matrix_sync(dst, fc0, B_, wmma::mem_row_major);
  wmma::store_matrix_sync(dst + 16, fc1, B_, wmma::mem_row_major);
}

// ---------------- LSTM cell (+ split-K reduce) ----------------
__global__ void k_cell(const float* __restrict__ bias) {
  int idx = blockIdx.x * blockDim.x + threadIdx.x;
  if (idx >= H_ * B_) return;
  int b = idx & 31, hid = idx >> 5;
  float ig = 0.f, fg = 0.f, gg = 0.f, og = 0.f;
#pragma unroll
  for (int ks = 0; ks < KSPL; ks++) {
    const float* p = g_part + (size_t)ks * GROWS * B_;
    ig += __ldcs(p + hid * B_ + b);
    fg += __ldcs(p + (H_ + hid) * B_ + b);
    gg += __ldcs(p + (2 * H_ + hid) * B_ + b);
    og += __ldcs(p + (3 * H_ + hid) * B_ + b);
  }
  ig += bias[hid]; fg += bias[H_ + hid]; gg += bias[2 * H_ + hid]; og += bias[3 * H_ + hid];
  float c  = g_c[idx];
  float cn = sigm(fg) * c + sigm(ig) * tanhf(gg);
  float hn = sigm(og) * tanhf(cn);
  g_c[idx] = cn;
  g_hf[b * H_ + hid] = hn;
  half hi = __float2half(hn);
  g_x_hi[(H_ + hid) * B_ + b] = hi;
  g_x_lo[(H_ + hid) * B_ + b] = __float2half(hn - __half2float(hi));
}

// ---- logits GEMM (bulk-copy A pipeline) + fused stats.  grid 500 ------------
__global__ void k_logits(const float* __restrict__ bout, int t, uint32_t k0, uint32_t k1) {
  extern __shared__ char smc[];
  half* Bf = (half*)smc;                       // 1024*BLD
  half* As = (half*)(smc + SM_B2);
  uint32_t smA   = (uint32_t)__cvta_generic_to_shared(As);
  uint32_t mbar0 = (uint32_t)__cvta_generic_to_shared(smc + SM_MBAR);
  int blk = blockIdx.x;
  if (t & 1) blk = (NBLK - 1) - blk;
  const int row0 = blk * LRB;
  const int tid = threadIdx.x, w = tid >> 5;
  const half* Bsrc = g_x_hi + H_ * B_;
  const int NCHK = H_ / KC;                    // 16

  if (tid == 0)
    for (int s = 0; s < STG; s++) MBAR_INIT(mbar0 + 8 * s, 1);
  __syncthreads();

  for (int i = tid; i < H_ * 4; i += 128) {
    int r = i >> 2, cc = i & 3;
    cp16(Bf + r * BLD + cc * 8, Bsrc + r * B_ + cc * 8);
  }
  CP_COMMIT();

  if (tid == 0)
    for (int c = 0; c < STG; c++) {
      MBAR_EXPECT(mbar0 + 8 * c, TILEB);
      bulkcp(smA + c * TILEB, g_wo2 + (size_t)(blk * 16 + c) * TILEH, TILEB, mbar0 + 8 * c);
    }
  CP_WAIT(0);
  __syncthreads();

  wmma::fragment<wmma::accumulator, 16, 16, 16, float> fc0, fc1;
  wmma::fill_fragment(fc0, 0.0f); wmma::fill_fragment(fc1, 0.0f);

  for (int c = 0; c < NCHK; c++) {
    int s = c % STG;
    mbar_wait(mbar0 + 8 * s, (c / STG) & 1);
    half* as = As + s * TILEH;
    wmma::fragment<wmma::matrix_a, 16, 16, 16, half, wmma::row_major> fa;
    wmma::fragment<wmma::matrix_b, 16, 16, 16, half, wmma::row_major> fb0, fb1;
#pragma unroll
    for (int k4 = 0; k4 < KC / 16; k4++) {
      int brow = c * KC + k4 * 16;
      wmma::load_matrix_sync(fa, as + (w * 16) * ALD + k4 * 16, ALD);
      wmma::load_matrix_sync(fb0, Bf + brow * BLD + 0, BLD);
      wmma::load_matrix_sync(fb1, Bf + brow * BLD + 16, BLD);
      wmma::mma_sync(fc0, fa, fb0, fc0);
      wmma::mma_sync(fc1, fa, fb1, fc1);
    }
    __syncthreads();
    if (c + STG < NCHK && tid == 0) {
      MBAR_EXPECT(mbar0 + 8 * s, TILEB);
      bulkcp(smA + s * TILEB, g_wo2 + (size_t)(blk * 16 + c + STG) * TILEH, TILEB, mbar0 + 8 * s);
    }
  }

  float* Ls = (float*)As;   // 64*36 floats = 9216B
  __syncthreads();
  wmma::store_matrix_sync(&Ls[(w * 16) * 36 + 0],  fc0, 36, wmma::mem_row_major);
  wmma::store_matrix_sync(&Ls[(w * 16) * 36 + 16], fc1, 36, wmma::mem_row_major);
  __syncthreads();

  for (int i = tid; i < LRB * B_; i += 128) {
    int b = i >> 6, r = i & 63;
    float lb = Ls[r * 36 + b] + bout[row0 + r];
    Ls[r * 36 + b] = lb;
    __stcs(&g_logits[b * V_ + row0 + r], lb);
  }
  __syncthreads();

  int c = tid >> 2, sub = tid & 3;
  float m = -INFINITY, s = 0.0f, v1 = -INFINITY, v2 = -INFINITY;
  int i1 = 0x7fffffff, i2 = 0x7fffffff;
  for (int r = sub; r < LRB; r += 4) {
    float lb = Ls[r * 36 + c];
    if (lb > m) { s = s * expf(m - lb) + 1.0f; m = lb; } else s += expf(lb - m);
    int v = row0 + r;
    float tv = lb + gumbel_of(k0, k1, (uint32_t)(c * V_ + v));
    if (tv > v1 || (tv == v1 && v < i1)) { v2 = v1; i2 = i1; v1 = tv; i1 = v; }
    else if (tv > v2 || (tv == v2 && v < i2)) { v2 = tv; i2 = v; }
  }
#pragma unroll
  for (int o = 1; o <= 2; o <<= 1) {
    float om = __shfl_xor_sync(0xffffffffu, m, o);
    float os = __shfl_xor_sync(0xffffffffu, s, o);
    float M = fmaxf(m, om);
    s = s * expf(m - M) + os * expf(om - M); m = M;
    float b1 = __shfl_xor_sync(0xffffffffu, v1, o);
    int   j1 = __shfl_xor_sync(0xffffffffu, i1, o);
    float b2 = __shfl_xor_sync(0xffffffffu, v2, o);
    int   j2 = __shfl_xor_sync(0xffffffffu, i2, o);
    merge2(v1, i1, v2, i2, b1, j1, b2, j2);
  }
  if (sub == 0) {
    __stcs(&g_cM[c * NBLK + blk], make_float2(m, s));
    __stcs(&g_cT[c * NBLK + blk], make_float4(v1, __int_as_float(i1), v2, __int_as_float(i2)));
  }
}

// ---- post: p write (blocks 0..15, __stwt) + finalize (block 16). grid (17,32)
__global__ void k_post(const float* __restrict__ wout, const float* __restrict__ bout,
                       const float* __restrict__ emb,
                       float* outS, float* __restrict__ outP,
                       int t, uint32_t k0, uint32_t k1) {
  int c = blockIdx.x, b = blockIdx.y, tid = threadIdx.x;
  __shared__ float rm[256], rs[256];
  float m = -INFINITY, s = 0.0f;
  for (int j = tid; j < NBLK; j += 256) {
    float2 a = __ldcs(&g_cM[b * NBLK + j]);
    float M = fmaxf(m, a.x);
    s = s * expf(m - M) + a.y * expf(a.x - M); m = M;
  }
  rm[tid] = m; rs[tid] = s;
  __syncthreads();
  for (int off = 128; off; off >>= 1) {
    if (tid < off) {
      float mA = rm[tid], mB = rm[tid + off];
      float M = fmaxf(mA, mB);
      rm[tid] = M;
      rs[tid] = rs[tid] * expf(mA - M) + rs[tid + off] * expf(mB - M);
    }
    __syncthreads();
  }
  float gm = rm[0], ginv = 1.0f / rs[0];
  __syncthreads();

  if (c < NPB) {
    int vbeg = c * VCH;
    float* op = outP + ((size_t)b * T_ + t) * V_;
    for (int v = vbeg + tid; v < vbeg + VCH; v += 256)
      __stwt(op + v, expf(__ldcs(&g_logits[b * V_ + v]) - gm) * ginv);
    return;
  }

  __shared__ float r1[256];
  __shared__ int   q1[256];
  float v1 = -INFINITY; int i1 = 0x7fffffff;
  for (int j = tid; j < NBLK; j += 256) {
    float4 a = __ldcs(&g_cT[b * NBLK + j]);
    float d2 = -INFINITY; int di = 0x7fffffff;
    merge2(v1, i1, d2, di, a.x, __float_as_int(a.y), a.z, __float_as_int(a.w));
  }
  r1[tid] = v1; q1[tid] = i1;
  __syncthreads();
  for (int off = 128; off; off >>= 1) {
    if (tid < off) {
      float bv = r1[tid + off]; int bi = q1[tid + off];
      if (bv > r1[tid] || (bv == r1[tid] && bi < q1[tid])) { r1[tid] = bv; q1[tid] = bi; }
    }
    __syncthreads();
  }
  float gtop = r1[0];
  __syncthreads();

  __shared__ int ncand;
  __shared__ int cands[64];
  __shared__ double cval[64];
  __shared__ int    cidx[64];
  __shared__ int    s_tok;
  if (tid == 0) ncand = 0;
  __syncthreads();
  float thr = gtop - DELTA;
  for (int j = tid; j < NBLK; j += 256) {
    float4 a = __ldcs(&g_cT[b * NBLK + j]);
    if (a.x >= thr) { int p = atomicAdd(&ncand, 1); if (p < 64) cands[p] = __float_as_int(a.y); }
    if (a.z >= thr) { int p = atomicAdd(&ncand, 1); if (p < 64) cands[p] = __float_as_int(a.w); }
  }
  __syncthreads();
  int n = ncand < 64 ? ncand : 64;
  int w = tid >> 5, lane = tid & 31;
  for (int ci = w; ci < n; ci += 8) {
    int v = cands[ci];
    const float4* wr4 = (const float4*)(wout + (size_t)v * H_);
    const float4* hr4 = (const float4*)(g_hf + b * H_);
    double acc = 0.0;
#pragma unroll
    for (int j = 0; j < 8; j++) {
      float4 a4 = __ldg(wr4 + lane + 32 * j);
      float4 b4 = hr4[lane + 32 * j];
      acc += (double)a4.x * b4.x + (double)a4.y * b4.y
           + (double)a4.z * b4.z + (double)a4.w * b4.w;
    }
    for (int o = 16; o; o >>= 1) acc += __shfl_down_sync(0xffffffffu, acc, o);
    if (lane == 0) {
      cval[ci] = acc + (double)bout[v] + (double)gumbel_of(k0, k1, (uint32_t)(b * V_ + v));
      cidx[ci] = v;
    }
  }
  __syncthreads();
  if (tid == 0) {
    double bv = -1e300; int bi = 0x7fffffff;
    for (int ci = 0; ci < n; ci++)
      if (cval[ci] > bv || (cval[ci] == bv && cidx[ci] < bi)) { bv = cval[ci]; bi = cidx[ci]; }
    s_tok = bi;
    g_s[b] = bi;
    if (outS) outS[b * T_ + t] = (float)bi;
  }
  __syncthreads();
  int tok = s_tok;
  for (int k = tid; k < EMB_; k += 256) {
    float val = emb[tok * EMB_ + k];
    half hi = __float2half(val);
    g_x_hi[k * B_ + b] = hi;
    g_x_lo[k * B_ + b] = __float2half(val - __half2float(hi));
  }
}

// ---------------- host ----------------
extern "C" void kernel_launch(void* const* d_in, const int* in_sizes, int n_in,
                              void* d_out, int out_size) {
  const float* z     = (const float*)d_in[0];
  const float* emb   = (const float*)d_in[1];
  const float* w_ih  = (const float*)d_in[2];
  const float* w_hh  = (const float*)d_in[3];
  const float* bias  = (const float*)d_in[4];
  const float* w_out = (const float*)d_in[5];
  const float* b_out = (const float*)d_in[6];
  const int*   sid   = (n_in > 7) ? (const int*)d_in[7] : nullptr;

  float* out  = (float*)d_out;
  float* outS = out;
  float* outP = out + B_ * T_;
  if (out_size == B_ * T_ * V_) { outS = nullptr; outP = out; }

  cudaFuncSetAttribute(k_gates,  cudaFuncAttributeMaxDynamicSharedMemorySize, SMEMSZ);
  cudaFuncSetAttribute(k_logits, cudaFuncAttributeMaxDynamicSharedMemorySize, SMEMSZ);

  k_conv_comb<<<2048, 256>>>(w_ih, w_hh);
  k_conv_wout<<<4096, 256>>>(w_out);
  k_init<<<(H_ * B_ + 255) / 256, 256>>>(z, sid, emb);

  for (int t = 0; t < T_; ++t) {
    uint32_t fk0, fk1;
    tf2x32(0u, 42u, 0u, (uint32_t)t, fk0, fk1);
    k_gates<<<dim3(GROWS / GRB, KSPL), 128, SMEMSZ>>>(t);
    k_cell<<<(H_ * B_ + 255) / 256, 256>>>(bias);
    k_logits<<<NBLK, 128, SMEMSZ>>>(b_out, t, fk0, fk1);
    k_post<<<dim3(NPB + 1, B_), 256>>>(w_out, b_out, emb, outS, outP, t, fk0, fk1);
  }
}

// round 15
// speedup vs baseline: 1.1189x; 1.1189x over previous
#include <cuda_runtime.h>
#include <cuda_fp16.h>
#include <mma.h>
#include <cstdint>
#include <math.h>

using namespace nvcuda;

#define B_    32
#define V_    32000
#define EMB_  512
#define H_    1024
#define T_    100
#define KG    2048
#define GROWS 4096
#define KSPL  4
#define GRB   64
#define LRB   64
#define NBLK  (V_ / LRB)     // 500
#define KC    64
#define STG   3
#define NPB   16
#define VCH   (V_ / NPB)
#define DELTA 0.05f

#define ALD   72             // padded row stride in halves (tile + smem)
#define BLD   40             // B smem row stride (halves)
#define TILEH (GRB * ALD)    // 4608 halves per tile
#define TILEB (TILEH * 2)    // 9216 bytes per tile

// gates dynamic smem layout (bytes)
#define G_BL  15360
#define G_AS  30720
#define G_MB  58368
#define G_SZ  58400
// logits dynamic smem layout (bytes)
#define L_AS  15360
#define L_MB  43008
#define L_SZ  43040

// ---------------- static device state ----------------
__device__ __align__(128) half  g_wchi2[64 * 32 * TILEH];          // 18.9 MB blob
__device__ __align__(128) half  g_wclo2[64 * 32 * TILEH];          // 18.9 MB blob
__device__ __align__(128) half  g_wo2[(size_t)NBLK * 16 * TILEH];  // 73.7 MB blob
__device__ __align__(128) half  g_x_hi[KG * B_];
__device__ __align__(128) half  g_x_lo[KG * B_];
__device__ __align__(128) float g_part[(size_t)KSPL * GROWS * B_]; // 2 MB
__device__ __align__(128) float g_logits[B_ * V_];
__device__ __align__(128) float g_c[H_ * B_];
__device__ __align__(128) float g_hf[B_ * H_];
__device__ int    g_s[B_];
__device__ float2 g_cM[B_ * NBLK];
__device__ float4 g_cT[B_ * NBLK];

// ---------------- async-copy / mbarrier helpers ----------------
__device__ __forceinline__ void cp16(void* sdst, const void* gsrc) {
  uint32_t d = (uint32_t)__cvta_generic_to_shared(sdst);
  asm volatile("cp.async.cg.shared.global [%0], [%1], 16;\n" :: "r"(d), "l"(gsrc));
}
#define CP_COMMIT() asm volatile("cp.async.commit_group;\n" ::: "memory")
#define CP_WAIT(n)  asm volatile("cp.async.wait_group %0;\n" :: "n"(n) : "memory")

#define MBAR_INIT(addr, cnt) \
  asm volatile("mbarrier.init.shared.b64 [%0], %1;" :: "r"(addr), "r"(cnt) : "memory")
#define MBAR_EXPECT(addr, bytes) \
  asm volatile("mbarrier.arrive.expect_tx.shared.b64 _, [%0], %1;" :: "r"(addr), "r"(bytes) : "memory")

__device__ __forceinline__ void mbar_wait(uint32_t mbar, uint32_t parity) {
  asm volatile(
      "{\n\t.reg .pred P;\n"
      "W%=:\n\tmbarrier.try_wait.parity.shared::cta.b64 P, [%0], %1;\n"
      "\t@!P bra W%=;\n}"
      :: "r"(mbar), "r"(parity) : "memory");
}
__device__ __forceinline__ void bulkcp(uint32_t sdst, const void* gsrc,
                                       uint32_t bytes, uint32_t mbar) {
  asm volatile(
      "cp.async.bulk.shared::cta.global.mbarrier::complete_tx::bytes [%0], [%1], %2, [%3];"
      :: "r"(sdst), "l"(gsrc), "r"(bytes), "r"(mbar) : "memory");
}

// ---------------- threefry / misc ----------------
__host__ __device__ inline void tf2x32(uint32_t k0, uint32_t k1, uint32_t x0, uint32_t x1,
                                       uint32_t &o0, uint32_t &o1) {
  uint32_t ks2 = k0 ^ k1 ^ 0x1BD11BDAu;
  x0 += k0; x1 += k1;
#define TF_R(r) do { x0 += x1; x1 = (x1 << (r)) | (x1 >> (32 - (r))); x1 ^= x0; } while (0)
  TF_R(13); TF_R(15); TF_R(26); TF_R(6);
  x0 += k1;  x1 += ks2 + 1u;
  TF_R(17); TF_R(29); TF_R(16); TF_R(24);
  x0 += ks2; x1 += k0 + 2u;
  TF_R(13); TF_R(15); TF_R(26); TF_R(6);
  x0 += k0;  x1 += k1 + 3u;
  TF_R(17); TF_R(29); TF_R(16); TF_R(24);
  x0 += k1;  x1 += ks2 + 4u;
  TF_R(13); TF_R(15); TF_R(26); TF_R(6);
  x0 += ks2; x1 += k0 + 5u;
#undef TF_R
  o0 = x0; o1 = x1;
}

__device__ __forceinline__ float gumbel_of(uint32_t k0, uint32_t k1, uint32_t i) {
  uint32_t a, b;
  tf2x32(k0, k1, 0u, i, a, b);
  uint32_t bits = a ^ b;
  float u = __uint_as_float((bits >> 9) | 0x3f800000u) - 1.0f;
  const float tiny = 1.17549435e-38f;
  float val = fmaxf(tiny, u * (1.0f - tiny) + tiny);
  return -logf(-logf(val));
}

__device__ __forceinline__ float sigm(float x) { return 1.0f / (1.0f + expf(-x)); }

__device__ __forceinline__ void merge2(float &v1, int &i1, float &v2, int &i2,
                                       float b1, int j1, float b2, int j2) {
  float n1, n2; int m1, m2;
  bool bf = (b1 > v1) || (b1 == v1 && j1 < i1);
  if (bf) { n1 = b1; m1 = j1; bool tk = (v1 > b2) || (v1 == b2 && i1 < j2);
            n2 = tk ? v1 : b2; m2 = tk ? i1 : j2; }
  else    { n1 = v1; m1 = i1; bool tk = (b1 > v2) || (b1 == v2 && j1 < i2);
            n2 = tk ? b1 : v2; m2 = tk ? j1 : i2; }
  v1 = n1; i1 = m1; v2 = n2; i2 = m2;
}

// ---------------- conversion into contiguous tiles ----------------
__global__ void k_conv_comb(const float* __restrict__ w_ih, const float* __restrict__ w_hh) {
  size_t total = (size_t)64 * 32 * (TILEH / 2);
  for (size_t p = blockIdx.x * blockDim.x + threadIdx.x; p < total;
       p += (size_t)gridDim.x * blockDim.x) {
    size_t tile = p / (TILEH / 2);
    int q = (int)(p % (TILEH / 2));
    int r = q / (ALD / 2), kp = (q % (ALD / 2)) * 2;
    int grp = (int)(tile >> 5), ck = (int)(tile & 31);
    half2 hi = __halves2half2(__float2half(0.f), __float2half(0.f));
    half2 lo = hi;
    if (kp < KC) {
      int col = ck * KC + kp;
      int sr = grp * GRB + r;
      float v0, v1;
      if (col < 1024) { v0 = __ldcs(w_ih + (size_t)sr * 1024 + col);
                        v1 = __ldcs(w_ih + (size_t)sr * 1024 + col + 1); }
      else            { v0 = __ldcs(w_hh + (size_t)sr * 1024 + col - 1024);
                        v1 = __ldcs(w_hh + (size_t)sr * 1024 + col - 1023); }
      half h0 = __float2half(v0), h1 = __float2half(v1);
      hi = __halves2half2(h0, h1);
      lo = __halves2half2(__float2half(v0 - __half2float(h0)),
                          __float2half(v1 - __half2float(h1)));
    }
    size_t off = tile * TILEH + (size_t)r * ALD + kp;
    *(half2*)&g_wchi2[off] = hi;
    *(half2*)&g_wclo2[off] = lo;
  }
}
__global__ void k_conv_wout(const float* __restrict__ w) {
  size_t total = (size_t)NBLK * 16 * (TILEH / 2);
  for (size_t p = blockIdx.x * blockDim.x + threadIdx.x; p < total;
       p += (size_t)gridDim.x * blockDim.x) {
    size_t tile = p / (TILEH / 2);
    int q = (int)(p % (TILEH / 2));
    int r = q / (ALD / 2), kp = (q % (ALD / 2)) * 2;
    int blk = (int)(tile >> 4), c = (int)(tile & 15);
    half2 h = __halves2half2(__float2half(0.f), __float2half(0.f));
    if (kp < KC) {
      const float* src = w + (size_t)(blk * LRB + r) * H_ + c * KC + kp;
      h = __halves2half2(__float2half(__ldcs(src)), __float2half(__ldcs(src + 1)));
    }
    *(half2*)&g_wo2[tile * TILEH + (size_t)r * ALD + kp] = h;
  }
}
__global__ void k_init(const float* __restrict__ z, const int* __restrict__ sid,
                       const float* __restrict__ emb) {
  int idx = blockIdx.x * blockDim.x + threadIdx.x;
  if (idx < H_ * B_) {
    g_c[idx] = 0.0f;
    g_x_hi[H_ * B_ + idx] = __float2half(0.0f);
    g_x_lo[H_ * B_ + idx] = __float2half(0.0f);
    int b = idx & 31, hid = idx >> 5;
    g_hf[b * H_ + hid] = 0.0f;
  }
  if (idx < EMB_ * B_) {
    int b = idx & 31, k = idx >> 5;
    float v = z[b * EMB_ + k];
    half hi = __float2half(v);
    g_x_hi[(EMB_ + k) * B_ + b] = hi;
    g_x_lo[(EMB_ + k) * B_ + b] = __float2half(v - __half2float(hi));
    int tok = sid ? sid[0] : 0;
    float e = emb[tok * EMB_ + k];
    half ehi = __float2half(e);
    g_x_hi[k * B_ + b] = ehi;
    g_x_lo[k * B_ + b] = __float2half(e - __half2float(ehi));
  }
  if (idx < B_) g_s[idx] = sid ? sid[0] : 0;
}

// ---- gates GEMM: bulkcp A-ring + cp.async B-staging.  grid (64, 4) ----------
// slices 0-1: Whi (k=(ks&1)*1024) vs xhi AND xlo;  2-3: Wlo vs xhi.
__global__ void k_gates(int t) {
  extern __shared__ char smc[];
  half* BhAll = (half*)smc;
  half* BlAll = (half*)(smc + G_BL);
  half* AsAll = (half*)(smc + G_AS);
  uint32_t smA   = (uint32_t)__cvta_generic_to_shared(AsAll);
  uint32_t mbar0 = (uint32_t)__cvta_generic_to_shared(smc + G_MB);
  int grp = blockIdx.x;
  if (t & 1) grp = 63 - grp;
  const int row0 = grp * GRB;
  const int ks = blockIdx.y;
  const int tid = threadIdx.x, w = tid >> 5;
  const bool hiPhase = ks < 2;
  const half* blob = hiPhase ? g_wchi2 : g_wclo2;
  const int kk0 = (ks & 1) * 1024;
  const int tbase = grp * 32 + (ks & 1) * 16;
  const int NCHK = 16;

  if (tid == 0)
    for (int s = 0; s < STG; s++) MBAR_INIT(mbar0 + 8 * s, 1);
  __syncthreads();

  auto issueB = [&](int c) {
    int s = c % STG, kk = kk0 + c * KC;
    half* bh = BhAll + s * KC * BLD;
    half* bl = BlAll + s * KC * BLD;
#pragma unroll
    for (int j = 0; j < 2; j++) {
      int idx = tid + 128 * j, r = idx >> 2, cc = idx & 3;
      cp16(bh + r * BLD + cc * 8, g_x_hi + (kk + r) * B_ + cc * 8);
      if (hiPhase)
        cp16(bl + r * BLD + cc * 8, g_x_lo + (kk + r) * B_ + cc * 8);
    }
    CP_COMMIT();
  };
  auto issueA = [&](int c) {   // tid 0 only
    int s = c % STG;
    MBAR_EXPECT(mbar0 + 8 * s, TILEB);
    bulkcp(smA + s * TILEB, blob + (size_t)(tbase + c) * TILEH, TILEB, mbar0 + 8 * s);
  };

  issueB(0); issueB(1); issueB(2);
  if (tid == 0) { issueA(0); issueA(1); issueA(2); }

  wmma::fragment<wmma::accumulator, 16, 16, 16, float> fc0, fc1;
  wmma::fill_fragment(fc0, 0.0f); wmma::fill_fragment(fc1, 0.0f);

  for (int c = 0; c < NCHK; c++) {
    if (c + STG < NCHK) { CP_WAIT(2); } else { CP_WAIT(0); }
    int s = c % STG;
    mbar_wait(mbar0 + 8 * s, (c / STG) & 1);
    __syncthreads();
    half* as = AsAll + s * TILEH;
    half* bh = BhAll + s * KC * BLD;
    half* bl = BlAll + s * KC * BLD;
    wmma::fragment<wmma::matrix_a, 16, 16, 16, half, wmma::row_major> fa;
    wmma::fragment<wmma::matrix_b, 16, 16, 16, half, wmma::row_major> fb0, fb1;
#pragma unroll
    for (int k4 = 0; k4 < KC / 16; k4++) {
      wmma::load_matrix_sync(fa, as + (w * 16) * ALD + k4 * 16, ALD);
      wmma::load_matrix_sync(fb0, bh + (k4 * 16) * BLD + 0, BLD);
      wmma::load_matrix_sync(fb1, bh + (k4 * 16) * BLD + 16, BLD);
      wmma::mma_sync(fc0, fa, fb0, fc0);
      wmma::mma_sync(fc1, fa, fb1, fc1);
      if (hiPhase) {
        wmma::load_matrix_sync(fb0, bl + (k4 * 16) * BLD + 0, BLD);
        wmma::load_matrix_sync(fb1, bl + (k4 * 16) * BLD + 16, BLD);
        wmma::mma_sync(fc0, fa, fb0, fc0);
        wmma::mma_sync(fc1, fa, fb1, fc1);
      }
    }
    __syncthreads();
    if (c + STG < NCHK) {
      issueB(c + STG);
      if (tid == 0) issueA(c + STG);
    }
  }
  float* dst = g_part + ((size_t)ks * GROWS + row0 + w * 16) * B_;
  wmma::store_matrix_sync(dst, fc0, B_, wmma::mem_row_major);
  wmma::store_matrix_sync(dst + 16, fc1, B_, wmma::mem_row_major);
}

// ---------------- LSTM cell (+ split-K reduce) ----------------
__global__ void k_cell(const float* __restrict__ bias) {
  int idx = blockIdx.x * blockDim.x + threadIdx.x;
  if (idx >= H_ * B_) return;
  int b = idx & 31, hid = idx >> 5;
  float ig = 0.f, fg = 0.f, gg = 0.f, og = 0.f;
#pragma unroll
  for (int ks = 0; ks < KSPL; ks++) {
    const float* p = g_part + (size_t)ks * GROWS * B_;
    ig += __ldcs(p + hid * B_ + b);
    fg += __ldcs(p + (H_ + hid) * B_ + b);
    gg += __ldcs(p + (2 * H_ + hid) * B_ + b);
    og += __ldcs(p + (3 * H_ + hid) * B_ + b);
  }
  ig += bias[hid]; fg += bias[H_ + hid]; gg += bias[2 * H_ + hid]; og += bias[3 * H_ + hid];
  float c  = g_c[idx];
  float cn = sigm(fg) * c + sigm(ig) * tanhf(gg);
  float hn = sigm(og) * tanhf(cn);
  g_c[idx] = cn;
  g_hf[b * H_ + hid] = hn;
  half hi = __float2half(hn);
  g_x_hi[(H_ + hid) * B_ + b] = hi;
  g_x_lo[(H_ + hid) * B_ + b] = __float2half(hn - __half2float(hi));
}

// ---- logits GEMM: bulkcp A-ring + cp.async B-staging + stats.  grid 500 -----
__global__ void k_logits(const float* __restrict__ bout, int t, uint32_t k0, uint32_t k1) {
  extern __shared__ char smc[];
  half* BsAll = (half*)smc;
  half* AsAll = (half*)(smc + L_AS);
  uint32_t smA   = (uint32_t)__cvta_generic_to_shared(AsAll);
  uint32_t mbar0 = (uint32_t)__cvta_generic_to_shared(smc + L_MB);
  int blk = blockIdx.x;
  if (t & 1) blk = (NBLK - 1) - blk;
  const int row0 = blk * LRB;
  const int tid = threadIdx.x, w = tid >> 5;
  const half* Bsrc = g_x_hi + H_ * B_;
  const int NCHK = H_ / KC;   // 16

  if (tid == 0)
    for (int s = 0; s < STG; s++) MBAR_INIT(mbar0 + 8 * s, 1);
  __syncthreads();

  auto issueB = [&](int c) {
    int s = c % STG, kk = c * KC;
    half* bs = BsAll + s * KC * BLD;
#pragma unroll
    for (int j = 0; j < 2; j++) {
      int idx = tid + 128 * j, r = idx >> 2, cc = idx & 3;
      cp16(bs + r * BLD + cc * 8, Bsrc + (kk + r) * B_ + cc * 8);
    }
    CP_COMMIT();
  };
  auto issueA = [&](int c) {   // tid 0 only
    int s = c % STG;
    MBAR_EXPECT(mbar0 + 8 * s, TILEB);
    bulkcp(smA + s * TILEB, g_wo2 + (size_t)(blk * 16 + c) * TILEH, TILEB, mbar0 + 8 * s);
  };

  issueB(0); issueB(1); issueB(2);
  if (tid == 0) { issueA(0); issueA(1); issueA(2); }

  wmma::fragment<wmma::accumulator, 16, 16, 16, float> fc0, fc1;
  wmma::fill_fragment(fc0, 0.0f); wmma::fill_fragment(fc1, 0.0f);

  for (int c = 0; c < NCHK; c++) {
    if (c + STG < NCHK) { CP_WAIT(2); } else { CP_WAIT(0); }
    int s = c % STG;
    mbar_wait(mbar0 + 8 * s, (c / STG) & 1);
    __syncthreads();
    half* as = AsAll + s * TILEH;
    half* bs = BsAll + s * KC * BLD;
    wmma::fragment<wmma::matrix_a, 16, 16, 16, half, wmma::row_major> fa;
    wmma::fragment<wmma::matrix_b, 16, 16, 16, half, wmma::row_major> fb0, fb1;
#pragma unroll
    for (int k4 = 0; k4 < KC / 16; k4++) {
      wmma::load_matrix_sync(fa, as + (w * 16) * ALD + k4 * 16, ALD);
      wmma::load_matrix_sync(fb0, bs + (k4 * 16) * BLD + 0, BLD);
      wmma::load_matrix_sync(fb1, bs + (k4 * 16) * BLD + 16, BLD);
      wmma::mma_sync(fc0, fa, fb0, fc0);
      wmma::mma_sync(fc1, fa, fb1, fc1);
    }
    __syncthreads();
    if (c + STG < NCHK) {
      issueB(c + STG);
      if (tid == 0) issueA(c + STG);
    }
  }

  float* Ls = (float*)AsAll;   // 64*36 floats = 9216B
  __syncthreads();
  wmma::store_matrix_sync(&Ls[(w * 16) * 36 + 0],  fc0, 36, wmma::mem_row_major);
  wmma::store_matrix_sync(&Ls[(w * 16) * 36 + 16], fc1, 36, wmma::mem_row_major);
  __syncthreads();

  for (int i = tid; i < LRB * B_; i += 128) {
    int b = i >> 6, r = i & 63;
    float lb = Ls[r * 36 + b] + bout[row0 + r];
    Ls[r * 36 + b] = lb;
    __stcs(&g_logits[b * V_ + row0 + r], lb);
  }
  __syncthreads();

  int c = tid >> 2, sub = tid & 3;
  float m = -INFINITY, s = 0.0f, v1 = -INFINITY, v2 = -INFINITY;
  int i1 = 0x7fffffff, i2 = 0x7fffffff;
  for (int r = sub; r < LRB; r += 4) {
    float lb = Ls[r * 36 + c];
    if (lb > m) { s = s * expf(m - lb) + 1.0f; m = lb; } else s += expf(lb - m);
    int v = row0 + r;
    float tv = lb + gumbel_of(k0, k1, (uint32_t)(c * V_ + v));
    if (tv > v1 || (tv == v1 && v < i1)) { v2 = v1; i2 = i1; v1 = tv; i1 = v; }
    else if (tv > v2 || (tv == v2 && v < i2)) { v2 = tv; i2 = v; }
  }
#pragma unroll
  for (int o = 1; o <= 2; o <<= 1) {
    float om = __shfl_xor_sync(0xffffffffu, m, o);
    float os = __shfl_xor_sync(0xffffffffu, s, o);
    float M = fmaxf(m, om);
    s = s * expf(m - M) + os * expf(om - M); m = M;
    float b1 = __shfl_xor_sync(0xffffffffu, v1, o);
    int   j1 = __shfl_xor_sync(0xffffffffu, i1, o);
    float b2 = __shfl_xor_sync(0xffffffffu, v2, o);
    int   j2 = __shfl_xor_sync(0xffffffffu, i2, o);
    merge2(v1, i1, v2, i2, b1, j1, b2, j2);
  }
  if (sub == 0) {
    __stcs(&g_cM[c * NBLK + blk], make_float2(m, s));
    __stcs(&g_cT[c * NBLK + blk], make_float4(v1, __int_as_float(i1), v2, __int_as_float(i2)));
  }
}

// ---- post: p write (blocks 0..15, __stwt) + finalize (block 16). grid (17,32)
__global__ void k_post(const float* __restrict__ wout, const float* __restrict__ bout,
                       const float* __restrict__ emb,
                       float* outS, float* __restrict__ outP,
                       int t, uint32_t k0, uint32_t k1) {
  int c = blockIdx.x, b = blockIdx.y, tid = threadIdx.x;
  __shared__ float rm[256], rs[256];
  float m = -INFINITY, s = 0.0f;
  for (int j = tid; j < NBLK; j += 256) {
    float2 a = __ldcs(&g_cM[b * NBLK + j]);
    float M = fmaxf(m, a.x);
    s = s * expf(m - M) + a.y * expf(a.x - M); m = M;
  }
  rm[tid] = m; rs[tid] = s;
  __syncthreads();
  for (int off = 128; off; off >>= 1) {
    if (tid < off) {
      float mA = rm[tid], mB = rm[tid + off];
      float M = fmaxf(mA, mB);
      rm[tid] = M;
      rs[tid] = rs[tid] * expf(mA - M) + rs[tid + off] * expf(mB - M);
    }
    __syncthreads();
  }
  float gm = rm[0], ginv = 1.0f / rs[0];
  __syncthreads();

  if (c < NPB) {
    int vbeg = c * VCH;
    float* op = outP + ((size_t)b * T_ + t) * V_;
    for (int v = vbeg + tid; v < vbeg + VCH; v += 256)
      __stwt(op + v, expf(__ldcs(&g_logits[b * V_ + v]) - gm) * ginv);
    return;
  }

  __shared__ float r1[256];
  __shared__ int   q1[256];
  float v1 = -INFINITY; int i1 = 0x7fffffff;
  for (int j = tid; j < NBLK; j += 256) {
    float4 a = __ldcs(&g_cT[b * NBLK + j]);
    float d2 = -INFINITY; int di = 0x7fffffff;
    merge2(v1, i1, d2, di, a.x, __float_as_int(a.y), a.z, __float_as_int(a.w));
  }
  r1[tid] = v1; q1[tid] = i1;
  __syncthreads();
  for (int off = 128; off; off >>= 1) {
    if (tid < off) {
      float bv = r1[tid + off]; int bi = q1[tid + off];
      if (bv > r1[tid] || (bv == r1[tid] && bi < q1[tid])) { r1[tid] = bv; q1[tid] = bi; }
    }
    __syncthreads();
  }
  float gtop = r1[0];
  __syncthreads();

  __shared__ int ncand;
  __shared__ int cands[64];
  __shared__ double cval[64];
  __shared__ int    cidx[64];
  __shared__ int    s_tok;
  if (tid == 0) ncand = 0;
  __syncthreads();
  float thr = gtop - DELTA;
  for (int j = tid; j < NBLK; j += 256) {
    float4 a = __ldcs(&g_cT[b * NBLK + j]);
    if (a.x >= thr) { int p = atomicAdd(&ncand, 1); if (p < 64) cands[p] = __float_as_int(a.y); }
    if (a.z >= thr) { int p = atomicAdd(&ncand, 1); if (p < 64) cands[p] = __float_as_int(a.w); }
  }
  __syncthreads();
  int n = ncand < 64 ? ncand : 64;
  int w = tid >> 5, lane = tid & 31;
  for (int ci = w; ci < n; ci += 8) {
    int v = cands[ci];
    const float4* wr4 = (const float4*)(wout + (size_t)v * H_);
    const float4* hr4 = (const float4*)(g_hf + b * H_);
    double acc = 0.0;
#pragma unroll
    for (int j = 0; j < 8; j++) {
      float4 a4 = __ldg(wr4 + lane + 32 * j);
      float4 b4 = hr4[lane + 32 * j];
      acc += (double)a4.x * b4.x + (double)a4.y * b4.y
           + (double)a4.z * b4.z + (double)a4.w * b4.w;
    }
    for (int o = 16; o; o >>= 1) acc += __shfl_down_sync(0xffffffffu, acc, o);
    if (lane == 0) {
      cval[ci] = acc + (double)bout[v] + (double)gumbel_of(k0, k1, (uint32_t)(b * V_ + v));
      cidx[ci] = v;
    }
  }
  __syncthreads();
  if (tid == 0) {
    double bv = -1e300; int bi = 0x7fffffff;
    for (int ci = 0; ci < n; ci++)
      if (cval[ci] > bv || (cval[ci] == bv && cidx[ci] < bi)) { bv = cval[ci]; bi = cidx[ci]; }
    s_tok = bi;
    g_s[b] = bi;
    if (outS) outS[b * T_ + t] = (float)bi;
  }
  __syncthreads();
  int tok = s_tok;
  for (int k = tid; k < EMB_; k += 256) {
    float val = emb[tok * EMB_ + k];
    half hi = __float2half(val);
    g_x_hi[k * B_ + b] = hi;
    g_x_lo[k * B_ + b] = __float2half(val - __half2float(hi));
  }
}

// ---------------- host ----------------
extern "C" void kernel_launch(void* const* d_in, const int* in_sizes, int n_in,
                              void* d_out, int out_size) {
  const float* z     = (const float*)d_in[0];
  const float* emb   = (const float*)d_in[1];
  const float* w_ih  = (const float*)d_in[2];
  const float* w_hh  = (const float*)d_in[3];
  const float* bias  = (const float*)d_in[4];
  const float* w_out = (const float*)d_in[5];
  const float* b_out = (const float*)d_in[6];
  const int*   sid   = (n_in > 7) ? (const int*)d_in[7] : nullptr;

  float* out  = (float*)d_out;
  float* outS = out;
  float* outP = out + B_ * T_;
  if (out_size == B_ * T_ * V_) { outS = nullptr; outP = out; }

  cudaFuncSetAttribute(k_gates,  cudaFuncAttributeMaxDynamicSharedMemorySize, G_SZ);
  cudaFuncSetAttribute(k_logits, cudaFuncAttributeMaxDynamicSharedMemorySize, L_SZ);

  k_conv_comb<<<2048, 256>>>(w_ih, w_hh);
  k_conv_wout<<<4096, 256>>>(w_out);
  k_init<<<(H_ * B_ + 255) / 256, 256>>>(z, sid, emb);

  for (int t = 0; t < T_; ++t) {
    uint32_t fk0, fk1;
    tf2x32(0u, 42u, 0u, (uint32_t)t, fk0, fk1);
    k_gates<<<dim3(GROWS / GRB, KSPL), 128, G_SZ>>>(t);
    k_cell<<<(H_ * B_ + 255) / 256, 256>>>(bias);
    k_logits<<<NBLK, 128, L_SZ>>>(b_out, t, fk0, fk1);
    k_post<<<dim3(NPB + 1, B_), 256>>>(w_out, b_out, emb, outS, outP, t, fk0, fk1);
  }
}

// round 16
// speedup vs baseline: 1.1950x; 1.0681x over previous
#include <cuda_runtime.h>
#include <cuda_fp16.h>
#include <mma.h>
#include <cstdint>
#include <math.h>

using namespace nvcuda;

#define B_    32
#define V_    32000
#define EMB_  512
#define H_    1024
#define T_    100
#define KG    2048
#define GROWS 4096
#define KSPL  4
#define GRB   64
#define LRB   64
#define NBLK  (V_ / LRB)     // 500
#define KC    64
#define STG   3
#define NPB   16
#define VCH   (V_ / NPB)
#define DELTA 0.05f

#define ALD   72             // A row stride in halves (tile + smem)
#define BLD   40             // B row stride in halves (global padded + smem)
#define XLD   40             // global x row stride (halves)
#define TILEH (GRB * ALD)    // 4608
#define TILEB (TILEH * 2)    // 9216 bytes
#define BSTGB 10240          // B stage bytes = 128 rows * 40 halves * 2

// gates dyn smem layout (bytes): Bh ring 2*10240 | Bl ring 2*10240 | A 3*9216 | mbars
#define G_BL  20480
#define G_AS  40960
#define G_MB  68608
#define G_SZ  68672
// logits dyn smem: Bs ring 2*10240 | A 3*9216 | mbars
#define L_AS  20480
#define L_MB  48128
#define L_SZ  48192

// ---------------- static device state ----------------
__device__ __align__(128) half  g_wchi2[64 * 32 * TILEH];          // 18.9 MB blob
__device__ __align__(128) half  g_wclo2[64 * 32 * TILEH];          // 18.9 MB blob
__device__ __align__(128) half  g_wo2[(size_t)NBLK * 16 * TILEH];  // 73.7 MB blob
__device__ __align__(128) half  g_xp_hi[KG * XLD];                 // padded x (hi)
__device__ __align__(128) half  g_xp_lo[KG * XLD];                 // padded x (lo)
__device__ __align__(128) float g_part[(size_t)KSPL * GROWS * B_]; // 2 MB
__device__ __align__(128) float g_logits[B_ * V_];
__device__ __align__(128) float g_c[H_ * B_];
__device__ __align__(128) float g_hf[B_ * H_];
__device__ int    g_s[B_];
__device__ float2 g_cM[B_ * NBLK];
__device__ float4 g_cT[B_ * NBLK];

// ---------------- mbarrier / bulk helpers ----------------
#define MBAR_INIT(addr, cnt) \
  asm volatile("mbarrier.init.shared.b64 [%0], %1;" :: "r"(addr), "r"(cnt) : "memory")
#define MBAR_EXPECT(addr, bytes) \
  asm volatile("mbarrier.arrive.expect_tx.shared.b64 _, [%0], %1;" :: "r"(addr), "r"(bytes) : "memory")

__device__ __forceinline__ void mbar_wait(uint32_t mbar, uint32_t parity) {
  asm volatile(
      "{\n\t.reg .pred P;\n"
      "W%=:\n\tmbarrier.try_wait.parity.shared::cta.b64 P, [%0], %1;\n"
      "\t@!P bra W%=;\n}"
      :: "r"(mbar), "r"(parity) : "memory");
}
__device__ __forceinline__ void bulkcp(uint32_t sdst, const void* gsrc,
                                       uint32_t bytes, uint32_t mbar) {
  asm volatile(
      "cp.async.bulk.shared::cta.global.mbarrier::complete_tx::bytes [%0], [%1], %2, [%3];"
      :: "r"(sdst), "l"(gsrc), "r"(bytes), "r"(mbar) : "memory");
}

// ---------------- threefry / misc ----------------
__host__ __device__ inline void tf2x32(uint32_t k0, uint32_t k1, uint32_t x0, uint32_t x1,
                                       uint32_t &o0, uint32_t &o1) {
  uint32_t ks2 = k0 ^ k1 ^ 0x1BD11BDAu;
  x0 += k0; x1 += k1;
#define TF_R(r) do { x0 += x1; x1 = (x1 << (r)) | (x1 >> (32 - (r))); x1 ^= x0; } while (0)
  TF_R(13); TF_R(15); TF_R(26); TF_R(6);
  x0 += k1;  x1 += ks2 + 1u;
  TF_R(17); TF_R(29); TF_R(16); TF_R(24);
  x0 += ks2; x1 += k0 + 2u;
  TF_R(13); TF_R(15); TF_R(26); TF_R(6);
  x0 += k0;  x1 += k1 + 3u;
  TF_R(17); TF_R(29); TF_R(16); TF_R(24);
  x0 += k1;  x1 += ks2 + 4u;
  TF_R(13); TF_R(15); TF_R(26); TF_R(6);
  x0 += ks2; x1 += k0 + 5u;
#undef TF_R
  o0 = x0; o1 = x1;
}

__device__ __forceinline__ float gumbel_of(uint32_t k0, uint32_t k1, uint32_t i) {
  uint32_t a, b;
  tf2x32(k0, k1, 0u, i, a, b);
  uint32_t bits = a ^ b;
  float u = __uint_as_float((bits >> 9) | 0x3f800000u) - 1.0f;
  const float tiny = 1.17549435e-38f;
  float val = fmaxf(tiny, u * (1.0f - tiny) + tiny);
  return -logf(-logf(val));
}

__device__ __forceinline__ float sigm(float x) { return 1.0f / (1.0f + expf(-x)); }

__device__ __forceinline__ void merge2(float &v1, int &i1, float &v2, int &i2,
                                       float b1, int j1, float b2, int j2) {
  float n1, n2; int m1, m2;
  bool bf = (b1 > v1) || (b1 == v1 && j1 < i1);
  if (bf) { n1 = b1; m1 = j1; bool tk = (v1 > b2) || (v1 == b2 && i1 < j2);
            n2 = tk ? v1 : b2; m2 = tk ? i1 : j2; }
  else    { n1 = v1; m1 = i1; bool tk = (b1 > v2) || (b1 == v2 && j1 < i2);
            n2 = tk ? b1 : v2; m2 = tk ? j1 : i2; }
  v1 = n1; i1 = m1; v2 = n2; i2 = m2;
}

// ---------------- conversion into contiguous tiles ----------------
__global__ void k_conv_comb(const float* __restrict__ w_ih, const float* __restrict__ w_hh) {
  size_t total = (size_t)64 * 32 * (TILEH / 2);
  for (size_t p = blockIdx.x * blockDim.x + threadIdx.x; p < total;
       p += (size_t)gridDim.x * blockDim.x) {
    size_t tile = p / (TILEH / 2);
    int q = (int)(p % (TILEH / 2));
    int r = q / (ALD / 2), kp = (q % (ALD / 2)) * 2;
    int grp = (int)(tile >> 5), ck = (int)(tile & 31);
    half2 hi = __halves2half2(__float2half(0.f), __float2half(0.f));
    half2 lo = hi;
    if (kp < KC) {
      int col = ck * KC + kp;
      int sr = grp * GRB + r;
      float v0, v1;
      if (col < 1024) { v0 = __ldcs(w_ih + (size_t)sr * 1024 + col);
                        v1 = __ldcs(w_ih + (size_t)sr * 1024 + col + 1); }
      else            { v0 = __ldcs(w_hh + (size_t)sr * 1024 + col - 1024);
                        v1 = __ldcs(w_hh + (size_t)sr * 1024 + col - 1023); }
      half h0 = __float2half(v0), h1 = __float2half(v1);
      hi = __halves2half2(h0, h1);
      lo = __halves2half2(__float2half(v0 - __half2float(h0)),
                          __float2half(v1 - __half2float(h1)));
    }
    size_t off = tile * TILEH + (size_t)r * ALD + kp;
    *(half2*)&g_wchi2[off] = hi;
    *(half2*)&g_wclo2[off] = lo;
  }
}
__global__ void k_conv_wout(const float* __restrict__ w) {
  size_t total = (size_t)NBLK * 16 * (TILEH / 2);
  for (size_t p = blockIdx.x * blockDim.x + threadIdx.x; p < total;
       p += (size_t)gridDim.x * blockDim.x) {
    size_t tile = p / (TILEH / 2);
    int q = (int)(p % (TILEH / 2));
    int r = q / (ALD / 2), kp = (q % (ALD / 2)) * 2;
    int blk = (int)(tile >> 4), c = (int)(tile & 15);
    half2 h = __halves2half2(__float2half(0.f), __float2half(0.f));
    if (kp < KC) {
      const float* src = w + (size_t)(blk * LRB + r) * H_ + c * KC + kp;
      h = __halves2half2(__float2half(__ldcs(src)), __float2half(__ldcs(src + 1)));
    }
    *(half2*)&g_wo2[tile * TILEH + (size_t)r * ALD + kp] = h;
  }
}
__global__ void k_init(const float* __restrict__ z, const int* __restrict__ sid,
                       const float* __restrict__ emb) {
  int idx = blockIdx.x * blockDim.x + threadIdx.x;
  if (idx < H_ * B_) {
    g_c[idx] = 0.0f;
    int b = idx & 31, hid = idx >> 5;
    g_xp_hi[(H_ + hid) * XLD + b] = __float2half(0.0f);
    g_xp_lo[(H_ + hid) * XLD + b] = __float2half(0.0f);
    g_hf[b * H_ + hid] = 0.0f;
  }
  if (idx < EMB_ * B_) {
    int b = idx & 31, k = idx >> 5;
    float v = z[b * EMB_ + k];
    half hi = __float2half(v);
    g_xp_hi[(EMB_ + k) * XLD + b] = hi;
    g_xp_lo[(EMB_ + k) * XLD + b] = __float2half(v - __half2float(hi));
    int tok = sid ? sid[0] : 0;
    float e = emb[tok * EMB_ + k];
    half ehi = __float2half(e);
    g_xp_hi[k * XLD + b] = ehi;
    g_xp_lo[k * XLD + b] = __float2half(e - __half2float(ehi));
  }
  if (idx < B_) g_s[idx] = sid ? sid[0] : 0;
}

// ---- gates GEMM: bulk A-ring + bulk B-ring.  grid (64, 4), block 128 --------
// slices 0-1: Whi (k=(ks&1)*1024) vs xhi AND xlo;  2-3: Wlo vs xhi.
__global__ void k_gates(int t) {
  extern __shared__ char smc[];
  half* BhR = (half*)smc;                      // 2 x 128 rows x BLD
  half* BlR = (half*)(smc + G_BL);
  half* AsAll = (half*)(smc + G_AS);
  uint32_t smBh  = (uint32_t)__cvta_generic_to_shared(BhR);
  uint32_t smBl  = (uint32_t)__cvta_generic_to_shared(BlR);
  uint32_t smA   = (uint32_t)__cvta_generic_to_shared(AsAll);
  uint32_t mbA   = (uint32_t)__cvta_generic_to_shared(smc + G_MB);
  uint32_t mbB   = mbA + 24;
  int grp = blockIdx.x;
  if (t & 1) grp = 63 - grp;
  const int row0 = grp * GRB;
  const int ks = blockIdx.y;
  const int tid = threadIdx.x, w = tid >> 5;
  const bool hiPhase = ks < 2;
  const half* blob = hiPhase ? g_wchi2 : g_wclo2;
  const int kk0 = (ks & 1) * 1024;
  const int tbase = grp * 32 + (ks & 1) * 16;
  const int NCHK = 16;

  if (tid == 0) {
    for (int s = 0; s < STG; s++) MBAR_INIT(mbA + 8 * s, 1);
    for (int s = 0; s < 2; s++)   MBAR_INIT(mbB + 8 * s, 1);
  }
  __syncthreads();

  auto issueA = [&](int c) {   // tid0
    int s = c % STG;
    MBAR_EXPECT(mbA + 8 * s, TILEB);
    bulkcp(smA + s * TILEB, blob + (size_t)(tbase + c) * TILEH, TILEB, mbA + 8 * s);
  };
  auto issueBst = [&](int st) {   // tid0; stage = 128 k-rows
    int slot = st & 1;
    uint32_t mb = mbB + 8 * slot;
    MBAR_EXPECT(mb, hiPhase ? 2 * BSTGB : BSTGB);
    bulkcp(smBh + slot * BSTGB, g_xp_hi + (size_t)(kk0 + st * 128) * XLD, BSTGB, mb);
    if (hiPhase)
      bulkcp(smBl + slot * BSTGB, g_xp_lo + (size_t)(kk0 + st * 128) * XLD, BSTGB, mb);
  };

  if (tid == 0) {
    issueA(0); issueA(1); issueA(2);
    issueBst(0); issueBst(1);
  }

  wmma::fragment<wmma::accumulator, 16, 16, 16, float> fc0, fc1;
  wmma::fill_fragment(fc0, 0.0f); wmma::fill_fragment(fc1, 0.0f);

  for (int c = 0; c < NCHK; c++) {
    int sA = c % STG;
    mbar_wait(mbA + 8 * sA, (c / 3) & 1);
    int sb = c >> 1, slot = sb & 1;
    if (!(c & 1)) mbar_wait(mbB + 8 * slot, (sb >> 1) & 1);
    __syncthreads();
    half* as = AsAll + sA * TILEH;
    half* bh = BhR + slot * (128 * BLD) + (c & 1) * (64 * BLD);
    half* bl = BlR + slot * (128 * BLD) + (c & 1) * (64 * BLD);
    wmma::fragment<wmma::matrix_a, 16, 16, 16, half, wmma::row_major> fa;
    wmma::fragment<wmma::matrix_b, 16, 16, 16, half, wmma::row_major> fb0, fb1;
#pragma unroll
    for (int k4 = 0; k4 < KC / 16; k4++) {
      wmma::load_matrix_sync(fa, as + (w * 16) * ALD + k4 * 16, ALD);
      wmma::load_matrix_sync(fb0, bh + (k4 * 16) * BLD + 0, BLD);
      wmma::load_matrix_sync(fb1, bh + (k4 * 16) * BLD + 16, BLD);
      wmma::mma_sync(fc0, fa, fb0, fc0);
      wmma::mma_sync(fc1, fa, fb1, fc1);
      if (hiPhase) {
        wmma::load_matrix_sync(fb0, bl + (k4 * 16) * BLD + 0, BLD);
        wmma::load_matrix_sync(fb1, bl + (k4 * 16) * BLD + 16, BLD);
        wmma::mma_sync(fc0, fa, fb0, fc0);
        wmma::mma_sync(fc1, fa, fb1, fc1);
      }
    }
    __syncthreads();
    if (tid == 0) {
      if (c + STG < NCHK) issueA(c + STG);
      if ((c & 1) && sb + 2 < 8) issueBst(sb + 2);
    }
  }
  float* dst = g_part + ((size_t)ks * GROWS + row0 + w * 16) * B_;
  wmma::store_matrix_sync(dst, fc0, B_, wmma::mem_row_major);
  wmma::store_matrix_sync(dst + 16, fc1, B_, wmma::mem_row_major);
}

// ---------------- LSTM cell (+ split-K reduce) ----------------
__global__ void k_cell(const float* __restrict__ bias) {
  int idx = blockIdx.x * blockDim.x + threadIdx.x;
  if (idx >= H_ * B_) return;
  int b = idx & 31, hid = idx >> 5;
  float ig = 0.f, fg = 0.f, gg = 0.f, og = 0.f;
#pragma unroll
  for (int ks = 0; ks < KSPL; ks++) {
    const float* p = g_part + (size_t)ks * GROWS * B_;
    ig += __ldcs(p + hid * B_ + b);
    fg += __ldcs(p + (H_ + hid) * B_ + b);
    gg += __ldcs(p + (2 * H_ + hid) * B_ + b);
    og += __ldcs(p + (3 * H_ + hid) * B_ + b);
  }
  ig += bias[hid]; fg += bias[H_ + hid]; gg += bias[2 * H_ + hid]; og += bias[3 * H_ + hid];
  float c  = g_c[idx];
  float cn = sigm(fg) * c + sigm(ig) * tanhf(gg);
  float hn = sigm(og) * tanhf(cn);
  g_c[idx] = cn;
  g_hf[b * H_ + hid] = hn;
  half hi = __float2half(hn);
  g_xp_hi[(H_ + hid) * XLD + b] = hi;
  g_xp_lo[(H_ + hid) * XLD + b] = __float2half(hn - __half2float(hi));
}

// ---- logits GEMM: bulk A-ring + bulk B-ring + stats.  grid 500 --------------
__global__ void k_logits(const float* __restrict__ bout, int t, uint32_t k0, uint32_t k1) {
  extern __shared__ char smc[];
  half* BsR = (half*)smc;                      // 2 x 128 rows x BLD
  half* AsAll = (half*)(smc + L_AS);
  uint32_t smB   = (uint32_t)__cvta_generic_to_shared(BsR);
  uint32_t smA   = (uint32_t)__cvta_generic_to_shared(AsAll);
  uint32_t mbA   = (uint32_t)__cvta_generic_to_shared(smc + L_MB);
  uint32_t mbB   = mbA + 24;
  int blk = blockIdx.x;
  if (t & 1) blk = (NBLK - 1) - blk;
  const int row0 = blk * LRB;
  const int tid = threadIdx.x, w = tid >> 5;
  const half* Bsrc = g_xp_hi + (size_t)H_ * XLD;    // h rows
  const int NCHK = H_ / KC;   // 16

  if (tid == 0) {
    for (int s = 0; s < STG; s++) MBAR_INIT(mbA + 8 * s, 1);
    for (int s = 0; s < 2; s++)   MBAR_INIT(mbB + 8 * s, 1);
  }
  __syncthreads();

  auto issueA = [&](int c) {   // tid0
    int s = c % STG;
    MBAR_EXPECT(mbA + 8 * s, TILEB);
    bulkcp(smA + s * TILEB, g_wo2 + (size_t)(blk * 16 + c) * TILEH, TILEB, mbA + 8 * s);
  };
  auto issueBst = [&](int st) {   // tid0
    int slot = st & 1;
    uint32_t mb = mbB + 8 * slot;
    MBAR_EXPECT(mb, BSTGB);
    bulkcp(smB + slot * BSTGB, Bsrc + (size_t)(st * 128) * XLD, BSTGB, mb);
  };

  if (tid == 0) {
    issueA(0); issueA(1); issueA(2);
    issueBst(0); issueBst(1);
  }

  wmma::fragment<wmma::accumulator, 16, 16, 16, float> fc0, fc1;
  wmma::fill_fragment(fc0, 0.0f); wmma::fill_fragment(fc1, 0.0f);

  for (int c = 0; c < NCHK; c++) {
    int sA = c % STG;
    mbar_wait(mbA + 8 * sA, (c / 3) & 1);
    int sb = c >> 1, slot = sb & 1;
    if (!(c & 1)) mbar_wait(mbB + 8 * slot, (sb >> 1) & 1);
    __syncthreads();
    half* as = AsAll + sA * TILEH;
    half* bs = BsR + slot * (128 * BLD) + (c & 1) * (64 * BLD);
    wmma::fragment<wmma::matrix_a, 16, 16, 16, half, wmma::row_major> fa;
    wmma::fragment<wmma::matrix_b, 16, 16, 16, half, wmma::row_major> fb0, fb1;
#pragma unroll
    for (int k4 = 0; k4 < KC / 16; k4++) {
      wmma::load_matrix_sync(fa, as + (w * 16) * ALD + k4 * 16, ALD);
      wmma::load_matrix_sync(fb0, bs + (k4 * 16) * BLD + 0, BLD);
      wmma::load_matrix_sync(fb1, bs + (k4 * 16) * BLD + 16, BLD);
      wmma::mma_sync(fc0, fa, fb0, fc0);
      wmma::mma_sync(fc1, fa, fb1, fc1);
    }
    __syncthreads();
    if (tid == 0) {
      if (c + STG < NCHK) issueA(c + STG);
      if ((c & 1) && sb + 2 < 8) issueBst(sb + 2);
    }
  }

  float* Ls = (float*)AsAll;   // 64*36 floats = 9216B
  __syncthreads();
  wmma::store_matrix_sync(&Ls[(w * 16) * 36 + 0],  fc0, 36, wmma::mem_row_major);
  wmma::store_matrix_sync(&Ls[(w * 16) * 36 + 16], fc1, 36, wmma::mem_row_major);
  __syncthreads();

  for (int i = tid; i < LRB * B_; i += 128) {
    int b = i >> 6, r = i & 63;
    float lb = Ls[r * 36 + b] + bout[row0 + r];
    Ls[r * 36 + b] = lb;
    __stcs(&g_logits[b * V_ + row0 + r], lb);
  }
  __syncthreads();

  int c = tid >> 2, sub = tid & 3;
  float m = -INFINITY, s = 0.0f, v1 = -INFINITY, v2 = -INFINITY;
  int i1 = 0x7fffffff, i2 = 0x7fffffff;
  for (int r = sub; r < LRB; r += 4) {
    float lb = Ls[r * 36 + c];
    if (lb > m) { s = s * expf(m - lb) + 1.0f; m = lb; } else s += expf(lb - m);
    int v = row0 + r;
    float tv = lb + gumbel_of(k0, k1, (uint32_t)(c * V_ + v));
    if (tv > v1 || (tv == v1 && v < i1)) { v2 = v1; i2 = i1; v1 = tv; i1 = v; }
    else if (tv > v2 || (tv == v2 && v < i2)) { v2 = tv; i2 = v; }
  }
#pragma unroll
  for (int o = 1; o <= 2; o <<= 1) {
    float om = __shfl_xor_sync(0xffffffffu, m, o);
    float os = __shfl_xor_sync(0xffffffffu, s, o);
    float M = fmaxf(m, om);
    s = s * expf(m - M) + os * expf(om - M); m = M;
    float b1 = __shfl_xor_sync(0xffffffffu, v1, o);
    int   j1 = __shfl_xor_sync(0xffffffffu, i1, o);
    float b2 = __shfl_xor_sync(0xffffffffu, v2, o);
    int   j2 = __shfl_xor_sync(0xffffffffu, i2, o);
    merge2(v1, i1, v2, i2, b1, j1, b2, j2);
  }
  if (sub == 0) {
    __stcs(&g_cM[c * NBLK + blk], make_float2(m, s));
    __stcs(&g_cT[c * NBLK + blk], make_float4(v1, __int_as_float(i1), v2, __int_as_float(i2)));
  }
}

// ---- post: p write (blocks 0..15, __stwt) + finalize (block 16). grid (17,32)
__global__ void k_post(const float* __restrict__ wout, const float* __restrict__ bout,
                       const float* __restrict__ emb,
                       float* outS, float* __restrict__ outP,
                       int t, uint32_t k0, uint32_t k1) {
  int c = blockIdx.x, b = blockIdx.y, tid = threadIdx.x;
  __shared__ float rm[256], rs[256];
  float m = -INFINITY, s = 0.0f;
  for (int j = tid; j < NBLK; j += 256) {
    float2 a = __ldcs(&g_cM[b * NBLK + j]);
    float M = fmaxf(m, a.x);
    s = s * expf(m - M) + a.y * expf(a.x - M); m = M;
  }
  rm[tid] = m; rs[tid] = s;
  __syncthreads();
  for (int off = 128; off; off >>= 1) {
    if (tid < off) {
      float mA = rm[tid], mB = rm[tid + off];
      float M = fmaxf(mA, mB);
      rm[tid] = M;
      rs[tid] = rs[tid] * expf(mA - M) + rs[tid + off] * expf(mB - M);
    }
    __syncthreads();
  }
  float gm = rm[0], ginv = 1.0f / rs[0];
  __syncthreads();

  if (c < NPB) {
    int vbeg = c * VCH;
    float* op = outP + ((size_t)b * T_ + t) * V_;
    for (int v = vbeg + tid; v < vbeg + VCH; v += 256)
      __stwt(op + v, expf(__ldcs(&g_logits[b * V_ + v]) - gm) * ginv);
    return;
  }

  __shared__ float r1[256];
  __shared__ int   q1[256];
  float v1 = -INFINITY; int i1 = 0x7fffffff;
  for (int j = tid; j < NBLK; j += 256) {
    float4 a = __ldcs(&g_cT[b * NBLK + j]);
    float d2 = -INFINITY; int di = 0x7fffffff;
    merge2(v1, i1, d2, di, a.x, __float_as_int(a.y), a.z, __float_as_int(a.w));
  }
  r1[tid] = v1; q1[tid] = i1;
  __syncthreads();
  for (int off = 128; off; off >>= 1) {
    if (tid < off) {
      float bv = r1[tid + off]; int bi = q1[tid + off];
      if (bv > r1[tid] || (bv == r1[tid] && bi < q1[tid])) { r1[tid] = bv; q1[tid] = bi; }
    }
    __syncthreads();
  }
  float gtop = r1[0];
  __syncthreads();

  __shared__ int ncand;
  __shared__ int cands[64];
  __shared__ double cval[64];
  __shared__ int    cidx[64];
  __shared__ int    s_tok;
  if (tid == 0) ncand = 0;
  __syncthreads();
  float thr = gtop - DELTA;
  for (int j = tid; j < NBLK; j += 256) {
    float4 a = __ldcs(&g_cT[b * NBLK + j]);
    if (a.x >= thr) { int p = atomicAdd(&ncand, 1); if (p < 64) cands[p] = __float_as_int(a.y); }
    if (a.z >= thr) { int p = atomicAdd(&ncand, 1); if (p < 64) cands[p] = __float_as_int(a.w); }
  }
  __syncthreads();
  int n = ncand < 64 ? ncand : 64;
  int w = tid >> 5, lane = tid & 31;
  for (int ci = w; ci < n; ci += 8) {
    int v = cands[ci];
    const float4* wr4 = (const float4*)(wout + (size_t)v * H_);
    const float4* hr4 = (const float4*)(g_hf + b * H_);
    double acc = 0.0;
#pragma unroll
    for (int j = 0; j < 8; j++) {
      float4 a4 = __ldg(wr4 + lane + 32 * j);
      float4 b4 = hr4[lane + 32 * j];
      acc += (double)a4.x * b4.x + (double)a4.y * b4.y
           + (double)a4.z * b4.z + (double)a4.w * b4.w;
    }
    for (int o = 16; o; o >>= 1) acc += __shfl_down_sync(0xffffffffu, acc, o);
    if (lane == 0) {
      cval[ci] = acc + (double)bout[v] + (double)gumbel_of(k0, k1, (uint32_t)(b * V_ + v));
      cidx[ci] = v;
    }
  }
  __syncthreads();
  if (tid == 0) {
    double bv = -1e300; int bi = 0x7fffffff;
    for (int ci = 0; ci < n; ci++)
      if (cval[ci] > bv || (cval[ci] == bv && cidx[ci] < bi)) { bv = cval[ci]; bi = cidx[ci]; }
    s_tok = bi;
    g_s[b] = bi;
    if (outS) outS[b * T_ + t] = (float)bi;
  }
  __syncthreads();
  int tok = s_tok;
  for (int k = tid; k < EMB_; k += 256) {
    float val = emb[tok * EMB_ + k];
    half hi = __float2half(val);
    g_xp_hi[k * XLD + b] = hi;
    g_xp_lo[k * XLD + b] = __float2half(val - __half2float(hi));
  }
}

// ---------------- host ----------------
extern "C" void kernel_launch(void* const* d_in, const int* in_sizes, int n_in,
                              void* d_out, int out_size) {
  const float* z     = (const float*)d_in[0];
  const float* emb   = (const float*)d_in[1];
  const float* w_ih  = (const float*)d_in[2];
  const float* w_hh  = (const float*)d_in[3];
  const float* bias  = (const float*)d_in[4];
  const float* w_out = (const float*)d_in[5];
  const float* b_out = (const float*)d_in[6];
  const int*   sid   = (n_in > 7) ? (const int*)d_in[7] : nullptr;

  float* out  = (float*)d_out;
  float* outS = out;
  float* outP = out + B_ * T_;
  if (out_size == B_ * T_ * V_) { outS = nullptr; outP = out; }

  cudaFuncSetAttribute(k_gates,  cudaFuncAttributeMaxDynamicSharedMemorySize, G_SZ);
  cudaFuncSetAttribute(k_logits, cudaFuncAttributeMaxDynamicSharedMemorySize, L_SZ);

  k_conv_comb<<<2048, 256>>>(w_ih, w_hh);
  k_conv_wout<<<4096, 256>>>(w_out);
  k_init<<<(H_ * B_ + 255) / 256, 256>>>(z, sid, emb);

  for (int t = 0; t < T_; ++t) {
    uint32_t fk0, fk1;
    tf2x32(0u, 42u, 0u, (uint32_t)t, fk0, fk1);
    k_gates<<<dim3(GROWS / GRB, KSPL), 128, G_SZ>>>(t);
    k_cell<<<(H_ * B_ + 255) / 256, 256>>>(bias);
    k_logits<<<NBLK, 128, L_SZ>>>(b_out, t, fk0, fk1);
    k_post<<<dim3(NPB + 1, B_), 256>>>(w_out, b_out, emb, outS, outP, t, fk0, fk1);
  }
}

// round 17
// speedup vs baseline: 1.2272x; 1.0269x over previous
#include <cuda_runtime.h>
#include <cuda_fp16.h>
#include <mma.h>
#include <cstdint>
#include <math.h>

using namespace nvcuda;

#define B_    32
#define V_    32000
#define EMB_  512
#define H_    1024
#define T_    100
#define KG    2048
#define GROWS 4096
#define KSPL  8
#define GRB   64
#define LRB   64
#define NBLK  (V_ / LRB)     // 500
#define KC    64
#define STG   3
#define NPB   16
#define VCH   (V_ / NPB)
#define DELTA 0.05f

#define ALD   72             // A row stride in halves (tile + smem)
#define BLD   40             // B row stride in halves (global padded + smem)
#define XLD   40             // global x row stride (halves)
#define TILEH (GRB * ALD)    // 4608
#define TILEB (TILEH * 2)    // 9216 bytes
#define BSTGB 10240          // B stage bytes = 128 rows * 40 halves * 2

// gates dyn smem layout (bytes): Bh ring 2*10240 | Bl ring 2*10240 | A 3*9216 | mbars
#define G_BL  20480
#define G_AS  40960
#define G_MB  68608
#define G_SZ  68672
// logits dyn smem: Bs ring 2*10240 | A 3*9216 | mbars
#define L_AS  20480
#define L_MB  48128
#define L_SZ  48192

// ---------------- static device state ----------------
__device__ __align__(128) half  g_wchi2[64 * 32 * TILEH];          // 18.9 MB blob
__device__ __align__(128) half  g_wclo2[64 * 32 * TILEH];          // 18.9 MB blob
__device__ __align__(128) half  g_wo2[(size_t)NBLK * 16 * TILEH];  // 73.7 MB blob
__device__ __align__(128) half  g_xp_hi[KG * XLD];                 // padded x (hi)
__device__ __align__(128) half  g_xp_lo[KG * XLD];                 // padded x (lo)
__device__ __align__(128) float g_part[(size_t)KSPL * GROWS * B_]; // 4 MB
__device__ __align__(128) float g_logits[B_ * V_];
__device__ __align__(128) float g_c[H_ * B_];
__device__ __align__(128) float g_hf[B_ * H_];
__device__ int    g_s[B_];
__device__ float2 g_cM[B_ * NBLK];
__device__ float4 g_cT[B_ * NBLK];

// ---------------- mbarrier / bulk helpers ----------------
#define MBAR_INIT(addr, cnt) \
  asm volatile("mbarrier.init.shared.b64 [%0], %1;" :: "r"(addr), "r"(cnt) : "memory")
#define MBAR_EXPECT(addr, bytes) \
  asm volatile("mbarrier.arrive.expect_tx.shared.b64 _, [%0], %1;" :: "r"(addr), "r"(bytes) : "memory")

__device__ __forceinline__ void mbar_wait(uint32_t mbar, uint32_t parity) {
  asm volatile(
      "{\n\t.reg .pred P;\n"
      "W%=:\n\tmbarrier.try_wait.parity.shared::cta.b64 P, [%0], %1;\n"
      "\t@!P bra W%=;\n}"
      :: "r"(mbar), "r"(parity) : "memory");
}
__device__ __forceinline__ void bulkcp(uint32_t sdst, const void* gsrc,
                                       uint32_t bytes, uint32_t mbar) {
  asm volatile(
      "cp.async.bulk.shared::cta.global.mbarrier::complete_tx::bytes [%0], [%1], %2, [%3];"
      :: "r"(sdst), "l"(gsrc), "r"(bytes), "r"(mbar) : "memory");
}

// ---------------- threefry / misc ----------------
__host__ __device__ inline void tf2x32(uint32_t k0, uint32_t k1, uint32_t x0, uint32_t x1,
                                       uint32_t &o0, uint32_t &o1) {
  uint32_t ks2 = k0 ^ k1 ^ 0x1BD11BDAu;
  x0 += k0; x1 += k1;
#define TF_R(r) do { x0 += x1; x1 = (x1 << (r)) | (x1 >> (32 - (r))); x1 ^= x0; } while (0)
  TF_R(13); TF_R(15); TF_R(26); TF_R(6);
  x0 += k1;  x1 += ks2 + 1u;
  TF_R(17); TF_R(29); TF_R(16); TF_R(24);
  x0 += ks2; x1 += k0 + 2u;
  TF_R(13); TF_R(15); TF_R(26); TF_R(6);
  x0 += k0;  x1 += k1 + 3u;
  TF_R(17); TF_R(29); TF_R(16); TF_R(24);
  x0 += k1;  x1 += ks2 + 4u;
  TF_R(13); TF_R(15); TF_R(26); TF_R(6);
  x0 += ks2; x1 += k0 + 5u;
#undef TF_R
  o0 = x0; o1 = x1;
}

__device__ __forceinline__ float gumbel_of(uint32_t k0, uint32_t k1, uint32_t i) {
  uint32_t a, b;
  tf2x32(k0, k1, 0u, i, a, b);
  uint32_t bits = a ^ b;
  float u = __uint_as_float((bits >> 9) | 0x3f800000u) - 1.0f;
  const float tiny = 1.17549435e-38f;
  float val = fmaxf(tiny, u * (1.0f - tiny) + tiny);
  return -logf(-logf(val));
}

__device__ __forceinline__ float sigm(float x) { return 1.0f / (1.0f + expf(-x)); }

__device__ __forceinline__ void merge2(float &v1, int &i1, float &v2, int &i2,
                                       float b1, int j1, float b2, int j2) {
  float n1, n2; int m1, m2;
  bool bf = (b1 > v1) || (b1 == v1 && j1 < i1);
  if (bf) { n1 = b1; m1 = j1; bool tk = (v1 > b2) || (v1 == b2 && i1 < j2);
            n2 = tk ? v1 : b2; m2 = tk ? i1 : j2; }
  else    { n1 = v1; m1 = i1; bool tk = (b1 > v2) || (b1 == v2 && j1 < i2);
            n2 = tk ? b1 : v2; m2 = tk ? j1 : i2; }
  v1 = n1; i1 = m1; v2 = n2; i2 = m2;
}

// ---------------- conversion into contiguous tiles ----------------
__global__ void k_conv_comb(const float* __restrict__ w_ih, const float* __restrict__ w_hh) {
  size_t total = (size_t)64 * 32 * (TILEH / 2);
  for (size_t p = blockIdx.x * blockDim.x + threadIdx.x; p < total;
       p += (size_t)gridDim.x * blockDim.x) {
    size_t tile = p / (TILEH / 2);
    int q = (int)(p % (TILEH / 2));
    int r = q / (ALD / 2), kp = (q % (ALD / 2)) * 2;
    int grp = (int)(tile >> 5), ck = (int)(tile & 31);
    half2 hi = __halves2half2(__float2half(0.f), __float2half(0.f));
    half2 lo = hi;
    if (kp < KC) {
      int col = ck * KC + kp;
      int sr = grp * GRB + r;
      float v0, v1;
      if (col < 1024) { v0 = __ldcs(w_ih + (size_t)sr * 1024 + col);
                        v1 = __ldcs(w_ih + (size_t)sr * 1024 + col + 1); }
      else            { v0 = __ldcs(w_hh + (size_t)sr * 1024 + col - 1024);
                        v1 = __ldcs(w_hh + (size_t)sr * 1024 + col - 1023); }
      half h0 = __float2half(v0), h1 = __float2half(v1);
      hi = __halves2half2(h0, h1);
      lo = __halves2half2(__float2half(v0 - __half2float(h0)),
                          __float2half(v1 - __half2float(h1)));
    }
    size_t off = tile * TILEH + (size_t)r * ALD + kp;
    *(half2*)&g_wchi2[off] = hi;
    *(half2*)&g_wclo2[off] = lo;
  }
}
__global__ void k_conv_wout(const float* __restrict__ w) {
  size_t total = (size_t)NBLK * 16 * (TILEH / 2);
  for (size_t p = blockIdx.x * blockDim.x + threadIdx.x; p < total;
       p += (size_t)gridDim.x * blockDim.x) {
    size_t tile = p / (TILEH / 2);
    int q = (int)(p % (TILEH / 2));
    int r = q / (ALD / 2), kp = (q % (ALD / 2)) * 2;
    int blk = (int)(tile >> 4), c = (int)(tile & 15);
    half2 h = __halves2half2(__float2half(0.f), __float2half(0.f));
    if (kp < KC) {
      const float* src = w + (size_t)(blk * LRB + r) * H_ + c * KC + kp;
      h = __halves2half2(__float2half(__ldcs(src)), __float2half(__ldcs(src + 1)));
    }
    *(half2*)&g_wo2[tile * TILEH + (size_t)r * ALD + kp] = h;
  }
}
__global__ void k_init(const float* __restrict__ z, const int* __restrict__ sid,
                       const float* __restrict__ emb) {
  int idx = blockIdx.x * blockDim.x + threadIdx.x;
  if (idx < H_ * B_) {
    g_c[idx] = 0.0f;
    int b = idx & 31, hid = idx >> 5;
    g_xp_hi[(H_ + hid) * XLD + b] = __float2half(0.0f);
    g_xp_lo[(H_ + hid) * XLD + b] = __float2half(0.0f);
    g_hf[b * H_ + hid] = 0.0f;
  }
  if (idx < EMB_ * B_) {
    int b = idx & 31, k = idx >> 5;
    float v = z[b * EMB_ + k];
    half hi = __float2half(v);
    g_xp_hi[(EMB_ + k) * XLD + b] = hi;
    g_xp_lo[(EMB_ + k) * XLD + b] = __float2half(v - __half2float(hi));
    int tok = sid ? sid[0] : 0;
    float e = emb[tok * EMB_ + k];
    half ehi = __float2half(e);
    g_xp_hi[k * XLD + b] = ehi;
    g_xp_lo[k * XLD + b] = __float2half(e - __half2float(ehi));
  }
  if (idx < B_) g_s[idx] = sid ? sid[0] : 0;
}

// ---- gates GEMM: bulk A-ring + bulk B-ring.  grid (64, 8), block 128 --------
// slices 0..3: Whi (k=(ks&3)*512) vs xhi AND xlo;  4..7: Wlo vs xhi.
__global__ void k_gates(int t) {
  extern __shared__ char smc[];
  half* BhR = (half*)smc;                      // 2 x 128 rows x BLD
  half* BlR = (half*)(smc + G_BL);
  half* AsAll = (half*)(smc + G_AS);
  uint32_t smBh  = (uint32_t)__cvta_generic_to_shared(BhR);
  uint32_t smBl  = (uint32_t)__cvta_generic_to_shared(BlR);
  uint32_t smA   = (uint32_t)__cvta_generic_to_shared(AsAll);
  uint32_t mbA   = (uint32_t)__cvta_generic_to_shared(smc + G_MB);
  uint32_t mbB   = mbA + 24;
  int grp = blockIdx.x;
  if (t & 1) grp = 63 - grp;
  const int row0 = grp * GRB;
  const int ks = blockIdx.y;
  const int tid = threadIdx.x, w = tid >> 5;
  const bool hiPhase = ks < 4;
  const half* blob = hiPhase ? g_wchi2 : g_wclo2;
  const int kk0 = (ks & 3) * 512;
  const int tbase = grp * 32 + (ks & 3) * 8;
  const int NCHK = 8;
  const int NBST = 4;                          // B stages (128 rows each)

  if (tid == 0) {
    for (int s = 0; s < STG; s++) MBAR_INIT(mbA + 8 * s, 1);
    for (int s = 0; s < 2; s++)   MBAR_INIT(mbB + 8 * s, 1);
  }
  __syncthreads();

  auto issueA = [&](int c) {   // tid0
    int s = c % STG;
    MBAR_EXPECT(mbA + 8 * s, TILEB);
    bulkcp(smA + s * TILEB, blob + (size_t)(tbase + c) * TILEH, TILEB, mbA + 8 * s);
  };
  auto issueBst = [&](int st) {   // tid0; stage = 128 k-rows
    int slot = st & 1;
    uint32_t mb = mbB + 8 * slot;
    MBAR_EXPECT(mb, hiPhase ? 2 * BSTGB : BSTGB);
    bulkcp(smBh + slot * BSTGB, g_xp_hi + (size_t)(kk0 + st * 128) * XLD, BSTGB, mb);
    if (hiPhase)
      bulkcp(smBl + slot * BSTGB, g_xp_lo + (size_t)(kk0 + st * 128) * XLD, BSTGB, mb);
  };

  if (tid == 0) {
    issueA(0); issueA(1); issueA(2);
    issueBst(0); issueBst(1);
  }

  wmma::fragment<wmma::accumulator, 16, 16, 16, float> fc0, fc1;
  wmma::fill_fragment(fc0, 0.0f); wmma::fill_fragment(fc1, 0.0f);

  for (int c = 0; c < NCHK; c++) {
    int sA = c % STG;
    mbar_wait(mbA + 8 * sA, (c / 3) & 1);
    int sb = c >> 1, slot = sb & 1;
    if (!(c & 1)) mbar_wait(mbB + 8 * slot, (sb >> 1) & 1);
    __syncthreads();
    half* as = AsAll + sA * TILEH;
    half* bh = BhR + slot * (128 * BLD) + (c & 1) * (64 * BLD);
    half* bl = BlR + slot * (128 * BLD) + (c & 1) * (64 * BLD);
    wmma::fragment<wmma::matrix_a, 16, 16, 16, half, wmma::row_major> fa;
    wmma::fragment<wmma::matrix_b, 16, 16, 16, half, wmma::row_major> fb0, fb1;
#pragma unroll
    for (int k4 = 0; k4 < KC / 16; k4++) {
      wmma::load_matrix_sync(fa, as + (w * 16) * ALD + k4 * 16, ALD);
      wmma::load_matrix_sync(fb0, bh + (k4 * 16) * BLD + 0, BLD);
      wmma::load_matrix_sync(fb1, bh + (k4 * 16) * BLD + 16, BLD);
      wmma::mma_sync(fc0, fa, fb0, fc0);
      wmma::mma_sync(fc1, fa, fb1, fc1);
      if (hiPhase) {
        wmma::load_matrix_sync(fb0, bl + (k4 * 16) * BLD + 0, BLD);
        wmma::load_matrix_sync(fb1, bl + (k4 * 16) * BLD + 16, BLD);
        wmma::mma_sync(fc0, fa, fb0, fc0);
        wmma::mma_sync(fc1, fa, fb1, fc1);
      }
    }
    __syncthreads();
    if (tid == 0) {
      if (c + STG < NCHK) issueA(c + STG);
      if ((c & 1) && sb + 2 < NBST) issueBst(sb + 2);
    }
  }
  float* dst = g_part + ((size_t)ks * GROWS + row0 + w * 16) * B_;
  wmma::store_matrix_sync(dst, fc0, B_, wmma::mem_row_major);
  wmma::store_matrix_sync(dst + 16, fc1, B_, wmma::mem_row_major);
}

// ---------------- LSTM cell (+ split-K reduce) ----------------
__global__ void k_cell(const float* __restrict__ bias) {
  int idx = blockIdx.x * blockDim.x + threadIdx.x;
  if (idx >= H_ * B_) return;
  int b = idx & 31, hid = idx >> 5;
  float ig = 0.f, fg = 0.f, gg = 0.f, og = 0.f;
#pragma unroll
  for (int ks = 0; ks < KSPL; ks++) {
    const float* p = g_part + (size_t)ks * GROWS * B_;
    ig += __ldcs(p + hid * B_ + b);
    fg += __ldcs(p + (H_ + hid) * B_ + b);
    gg += __ldcs(p + (2 * H_ + hid) * B_ + b);
    og += __ldcs(p + (3 * H_ + hid) * B_ + b);
  }
  ig += bias[hid]; fg += bias[H_ + hid]; gg += bias[2 * H_ + hid]; og += bias[3 * H_ + hid];
  float c  = g_c[idx];
  float cn = sigm(fg) * c + sigm(ig) * tanhf(gg);
  float hn = sigm(og) * tanhf(cn);
  g_c[idx] = cn;
  g_hf[b * H_ + hid] = hn;
  half hi = __float2half(hn);
  g_xp_hi[(H_ + hid) * XLD + b] = hi;
  g_xp_lo[(H_ + hid) * XLD + b] = __float2half(hn - __half2float(hi));
}

// ---- logits GEMM: bulk A-ring + bulk B-ring + stats.  grid 500 --------------
__global__ void k_logits(const float* __restrict__ bout, int t, uint32_t k0, uint32_t k1) {
  extern __shared__ char smc[];
  half* BsR = (half*)smc;                      // 2 x 128 rows x BLD
  half* AsAll = (half*)(smc + L_AS);
  uint32_t smB   = (uint32_t)__cvta_generic_to_shared(BsR);
  uint32_t smA   = (uint32_t)__cvta_generic_to_shared(AsAll);
  uint32_t mbA   = (uint32_t)__cvta_generic_to_shared(smc + L_MB);
  uint32_t mbB   = mbA + 24;
  int blk = blockIdx.x;
  if (t & 1) blk = (NBLK - 1) - blk;
  const int row0 = blk * LRB;
  const int tid = threadIdx.x, w = tid >> 5;
  const half* Bsrc = g_xp_hi + (size_t)H_ * XLD;    // h rows
  const int NCHK = H_ / KC;   // 16

  if (tid == 0) {
    for (int s = 0; s < STG; s++) MBAR_INIT(mbA + 8 * s, 1);
    for (int s = 0; s < 2; s++)   MBAR_INIT(mbB + 8 * s, 1);
  }
  __syncthreads();

  auto issueA = [&](int c) {   // tid0
    int s = c % STG;
    MBAR_EXPECT(mbA + 8 * s, TILEB);
    bulkcp(smA + s * TILEB, g_wo2 + (size_t)(blk * 16 + c) * TILEH, TILEB, mbA + 8 * s);
  };
  auto issueBst = [&](int st) {   // tid0
    int slot = st & 1;
    uint32_t mb = mbB + 8 * slot;
    MBAR_EXPECT(mb, BSTGB);
    bulkcp(smB + slot * BSTGB, Bsrc + (size_t)(st * 128) * XLD, BSTGB, mb);
  };

  if (tid == 0) {
    issueA(0); issueA(1); issueA(2);
    issueBst(0); issueBst(1);
  }

  wmma::fragment<wmma::accumulator, 16, 16, 16, float> fc0, fc1;
  wmma::fill_fragment(fc0, 0.0f); wmma::fill_fragment(fc1, 0.0f);

  for (int c = 0; c < NCHK; c++) {
    int sA = c % STG;
    mbar_wait(mbA + 8 * sA, (c / 3) & 1);
    int sb = c >> 1, slot = sb & 1;
    if (!(c & 1)) mbar_wait(mbB + 8 * slot, (sb >> 1) & 1);
    __syncthreads();
    half* as = AsAll + sA * TILEH;
    half* bs = BsR + slot * (128 * BLD) + (c & 1) * (64 * BLD);
    wmma::fragment<wmma::matrix_a, 16, 16, 16, half, wmma::row_major> fa;
    wmma::fragment<wmma::matrix_b, 16, 16, 16, half, wmma::row_major> fb0, fb1;
#pragma unroll
    for (int k4 = 0; k4 < KC / 16; k4++) {
      wmma::load_matrix_sync(fa, as + (w * 16) * ALD + k4 * 16, ALD);
      wmma::load_matrix_sync(fb0, bs + (k4 * 16) * BLD + 0, BLD);
      wmma::load_matrix_sync(fb1, bs + (k4 * 16) * BLD + 16, BLD);
      wmma::mma_sync(fc0, fa, fb0, fc0);
      wmma::mma_sync(fc1, fa, fb1, fc1);
    }
    __syncthreads();
    if (tid == 0) {
      if (c + STG < NCHK) issueA(c + STG);
      if ((c & 1) && sb + 2 < 8) issueBst(sb + 2);
    }
  }

  float* Ls = (float*)AsAll;   // 64*36 floats = 9216B
  __syncthreads();
  wmma::store_matrix_sync(&Ls[(w * 16) * 36 + 0],  fc0, 36, wmma::mem_row_major);
  wmma::store_matrix_sync(&Ls[(w * 16) * 36 + 16], fc1, 36, wmma::mem_row_major);
  __syncthreads();

  for (int i = tid; i < LRB * B_; i += 128) {
    int b = i >> 6, r = i & 63;
    float lb = Ls[r * 36 + b] + bout[row0 + r];
    Ls[r * 36 + b] = lb;
    __stcs(&g_logits[b * V_ + row0 + r], lb);
  }
  __syncthreads();

  int c = tid >> 2, sub = tid & 3;
  float m = -INFINITY, s = 0.0f, v1 = -INFINITY, v2 = -INFINITY;
  int i1 = 0x7fffffff, i2 = 0x7fffffff;
  for (int r = sub; r < LRB; r += 4) {
    float lb = Ls[r * 36 + c];
    if (lb > m) { s = s * expf(m - lb) + 1.0f; m = lb; } else s += expf(lb - m);
    int v = row0 + r;
    float tv = lb + gumbel_of(k0, k1, (uint32_t)(c * V_ + v));
    if (tv > v1 || (tv == v1 && v < i1)) { v2 = v1; i2 = i1; v1 = tv; i1 = v; }
    else if (tv > v2 || (tv == v2 && v < i2)) { v2 = tv; i2 = v; }
  }
#pragma unroll
  for (int o = 1; o <= 2; o <<= 1) {
    float om = __shfl_xor_sync(0xffffffffu, m, o);
    float os = __shfl_xor_sync(0xffffffffu, s, o);
    float M = fmaxf(m, om);
    s = s * expf(m - M) + os * expf(om - M); m = M;
    float b1 = __shfl_xor_sync(0xffffffffu, v1, o);
    int   j1 = __shfl_xor_sync(0xffffffffu, i1, o);
    float b2 = __shfl_xor_sync(0xffffffffu, v2, o);
    int   j2 = __shfl_xor_sync(0xffffffffu, i2, o);
    merge2(v1, i1, v2, i2, b1, j1, b2, j2);
  }
  if (sub == 0) {
    __stcs(&g_cM[c * NBLK + blk], make_float2(m, s));
    __stcs(&g_cT[c * NBLK + blk], make_float4(v1, __int_as_float(i1), v2, __int_as_float(i2)));
  }
}

// ---- post: p write (blocks 0..15, __stwt) + finalize (block 16). grid (17,32)
__global__ void k_post(const float* __restrict__ wout, const float* __restrict__ bout,
                       const float* __restrict__ emb,
                       float* outS, float* __restrict__ outP,
                       int t, uint32_t k0, uint32_t k1) {
  int c = blockIdx.x, b = blockIdx.y, tid = threadIdx.x;
  __shared__ float rm[256], rs[256];
  float m = -INFINITY, s = 0.0f;
  for (int j = tid; j < NBLK; j += 256) {
    float2 a = __ldcs(&g_cM[b * NBLK + j]);
    float M = fmaxf(m, a.x);
    s = s * expf(m - M) + a.y * expf(a.x - M); m = M;
  }
  rm[tid] = m; rs[tid] = s;
  __syncthreads();
  for (int off = 128; off; off >>= 1) {
    if (tid < off) {
      float mA = rm[tid], mB = rm[tid + off];
      float M = fmaxf(mA, mB);
      rm[tid] = M;
      rs[tid] = rs[tid] * expf(mA - M) + rs[tid + off] * expf(mB - M);
    }
    __syncthreads();
  }
  float gm = rm[0], ginv = 1.0f / rs[0];
  __syncthreads();

  if (c < NPB) {
    int vbeg = c * VCH;
    float* op = outP + ((size_t)b * T_ + t) * V_;
    for (int v = vbeg + tid; v < vbeg + VCH; v += 256)
      __stwt(op + v, expf(__ldcs(&g_logits[b * V_ + v]) - gm) * ginv);
    return;
  }

  __shared__ float r1[256];
  __shared__ int   q1[256];
  float v1 = -INFINITY; int i1 = 0x7fffffff;
  for (int j = tid; j < NBLK; j += 256) {
    float4 a = __ldcs(&g_cT[b * NBLK + j]);
    float d2 = -INFINITY; int di = 0x7fffffff;
    merge2(v1, i1, d2, di, a.x, __float_as_int(a.y), a.z, __float_as_int(a.w));
  }
  r1[tid] = v1; q1[tid] = i1;
  __syncthreads();
  for (int off = 128; off; off >>= 1) {
    if (tid < off) {
      float bv = r1[tid + off]; int bi = q1[tid + off];
      if (bv > r1[tid] || (bv == r1[tid] && bi < q1[tid])) { r1[tid] = bv; q1[tid] = bi; }
    }
    __syncthreads();
  }
  float gtop = r1[0];
  __syncthreads();

  __shared__ int ncand;
  __shared__ int cands[64];
  __shared__ double cval[64];
  __shared__ int    cidx[64];
  __shared__ int    s_tok;
  if (tid == 0) ncand = 0;
  __syncthreads();
  float thr = gtop - DELTA;
  for (int j = tid; j < NBLK; j += 256) {
    float4 a = __ldcs(&g_cT[b * NBLK + j]);
    if (a.x >= thr) { int p = atomicAdd(&ncand, 1); if (p < 64) cands[p] = __float_as_int(a.y); }
    if (a.z >= thr) { int p = atomicAdd(&ncand, 1); if (p < 64) cands[p] = __float_as_int(a.w); }
  }
  __syncthreads();
  int n = ncand < 64 ? ncand : 64;
  int w = tid >> 5, lane = tid & 31;
  for (int ci = w; ci < n; ci += 8) {
    int v = cands[ci];
    const float4* wr4 = (const float4*)(wout + (size_t)v * H_);
    const float4* hr4 = (const float4*)(g_hf + b * H_);
    double acc = 0.0;
#pragma unroll
    for (int j = 0; j < 8; j++) {
      float4 a4 = __ldg(wr4 + lane + 32 * j);
      float4 b4 = hr4[lane + 32 * j];
      acc += (double)a4.x * b4.x + (double)a4.y * b4.y
           + (double)a4.z * b4.z + (double)a4.w * b4.w;
    }
    for (int o = 16; o; o >>= 1) acc += __shfl_down_sync(0xffffffffu, acc, o);
    if (lane == 0) {
      cval[ci] = acc + (double)bout[v] + (double)gumbel_of(k0, k1, (uint32_t)(b * V_ + v));
      cidx[ci] = v;
    }
  }
  __syncthreads();
  if (tid == 0) {
    double bv = -1e300; int bi = 0x7fffffff;
    for (int ci = 0; ci < n; ci++)
      if (cval[ci] > bv || (cval[ci] == bv && cidx[ci] < bi)) { bv = cval[ci]; bi = cidx[ci]; }
    s_tok = bi;
    g_s[b] = bi;
    if (outS) outS[b * T_ + t] = (float)bi;
  }
  __syncthreads();
  int tok = s_tok;
  for (int k = tid; k < EMB_; k += 256) {
    float val = emb[tok * EMB_ + k];
    half hi = __float2half(val);
    g_xp_hi[k * XLD + b] = hi;
    g_xp_lo[k * XLD + b] = __float2half(val - __half2float(hi));
  }
}

// ---------------- host ----------------
extern "C" void kernel_launch(void* const* d_in, const int* in_sizes, int n_in,
                              void* d_out, int out_size) {
  const float* z     = (const float*)d_in[0];
  const float* emb   = (const float*)d_in[1];
  const float* w_ih  = (const float*)d_in[2];
  const float* w_hh  = (const float*)d_in[3];
  const float* bias  = (const float*)d_in[4];
  const float* w_out = (const float*)d_in[5];
  const float* b_out = (const float*)d_in[6];
  const int*   sid   = (n_in > 7) ? (const int*)d_in[7] : nullptr;

  float* out  = (float*)d_out;
  float* outS = out;
  float* outP = out + B_ * T_;
  if (out_size == B_ * T_ * V_) { outS = nullptr; outP = out; }

  cudaFuncSetAttribute(k_gates,  cudaFuncAttributeMaxDynamicSharedMemorySize, G_SZ);
  cudaFuncSetAttribute(k_logits, cudaFuncAttributeMaxDynamicSharedMemorySize, L_SZ);

  k_conv_comb<<<2048, 256>>>(w_ih, w_hh);
  k_conv_wout<<<4096, 256>>>(w_out);
  k_init<<<(H_ * B_ + 255) / 256, 256>>>(z, sid, emb);

  for (int t = 0; t < T_; ++t) {
    uint32_t fk0, fk1;
    tf2x32(0u, 42u, 0u, (uint32_t)t, fk0, fk1);
    k_gates<<<dim3(GROWS / GRB, KSPL), 128, G_SZ>>>(t);
    k_cell<<<(H_ * B_ + 255) / 256, 256>>>(bias);
    k_logits<<<NBLK, 128, L_SZ>>>(b_out, t, fk0, fk1);
    k_post<<<dim3(NPB + 1, B_), 256>>>(w_out, b_out, emb, outS, outP, t, fk0, fk1);
  }
}